// round 13
// baseline (speedup 1.0000x reference)
#include <cuda_runtime.h>
#include <cuda_bf16.h>
#include <math.h>
#include <stdint.h>

#define S_LEN   2048
#define DMODEL  1024
#define NHEADS  16
#define DK      64
#define BATCH   2
#define NTOK    (BATCH * S_LEN)
#define BHALL   (BATCH * NHEADS)
#define LOG2E   1.44269504f

__device__ __align__(256) __nv_bfloat16 g_Qh[BHALL * S_LEN * DK];
__device__ __align__(256) __nv_bfloat16 g_Ql[BHALL * S_LEN * DK];
__device__ __align__(256) __nv_bfloat16 g_Kh[BHALL * S_LEN * DK];
__device__ __align__(256) __nv_bfloat16 g_Kl[BHALL * S_LEN * DK];
__device__ __align__(256) __nv_bfloat16 g_Vh[BHALL * S_LEN * DK];
__device__ __align__(256) __nv_bfloat16 g_Vl[BHALL * S_LEN * DK];
__device__ __align__(256) __nv_bfloat16 g_Oh[NTOK * DMODEL];
__device__ __align__(256) __nv_bfloat16 g_Ol[NTOK * DMODEL];
__device__ __align__(256) __nv_bfloat16 g_xh[NTOK * DMODEL];
__device__ __align__(256) __nv_bfloat16 g_xl[NTOK * DMODEL];
__device__ __align__(256) __nv_bfloat16 g_WTh[4 * DMODEL * DMODEL];  // [z][n][k]
__device__ __align__(256) __nv_bfloat16 g_WTl[4 * DMODEL * DMODEL];
__device__ float g_cs[BHALL * S_LEN];
__device__ float g_sn[BHALL * S_LEN];

// ============================ helpers ============================
__device__ __forceinline__ unsigned sptr(const void* p) {
    return (unsigned)__cvta_generic_to_shared(p);
}
__device__ __forceinline__ void ldsm_x4(unsigned r[4], unsigned sa) {
    asm volatile("ldmatrix.sync.aligned.m8n8.x4.shared.b16 {%0,%1,%2,%3}, [%4];"
                 : "=r"(r[0]), "=r"(r[1]), "=r"(r[2]), "=r"(r[3]) : "r"(sa));
}
__device__ __forceinline__ void ldsm_x4t(unsigned r[4], unsigned sa) {
    asm volatile("ldmatrix.sync.aligned.m8n8.x4.trans.shared.b16 {%0,%1,%2,%3}, [%4];"
                 : "=r"(r[0]), "=r"(r[1]), "=r"(r[2]), "=r"(r[3]) : "r"(sa));
}
__device__ __forceinline__ void mma_bf16(float c[4], const unsigned a[4], const unsigned b[2]) {
    asm volatile(
        "mma.sync.aligned.m16n8k16.row.col.f32.bf16.bf16.f32 "
        "{%0,%1,%2,%3}, {%4,%5,%6,%7}, {%8,%9}, {%0,%1,%2,%3};"
        : "+f"(c[0]), "+f"(c[1]), "+f"(c[2]), "+f"(c[3])
        : "r"(a[0]), "r"(a[1]), "r"(a[2]), "r"(a[3]), "r"(b[0]), "r"(b[1]));
}
__device__ __forceinline__ void cpa16(unsigned d, const void* s) {
    asm volatile("cp.async.cg.shared.global [%0], [%1], 16;" :: "r"(d), "l"(s));
}
__device__ __forceinline__ void cp_commit() { asm volatile("cp.async.commit_group;"); }
template <int N> __device__ __forceinline__ void cp_wait() {
    asm volatile("cp.async.wait_group %0;" :: "n"(N));
}
__device__ __forceinline__ unsigned packbf(float e0, float e1) {
    unsigned r;
    asm("cvt.rn.bf16x2.f32 %0, %1, %2;" : "=r"(r) : "f"(e1), "f"(e0));
    return r;
}
__device__ __forceinline__ void hilo2(float e0, float e1, unsigned& hi, unsigned& lo) {
    hi = packbf(e0, e1);
    const float f0 = __uint_as_float(hi << 16);
    const float f1 = __uint_as_float(hi & 0xffff0000u);
    lo = packbf(e0 - f0, e1 - f1);
}
__device__ __forceinline__ float ex2(float x) {
    float r;
    asm("ex2.approx.f32 %0, %1;" : "=f"(r) : "f"(x));
    return r;
}

// ============================ prep kernels ============================
__global__ void __launch_bounds__(256) prep_x(const float* __restrict__ x)
{
    const int i = blockIdx.x * 256 + threadIdx.x;
    const float4 v = reinterpret_cast<const float4*>(x)[i];
    unsigned h01, h23, l01, l23;
    hilo2(v.x, v.y, h01, l01);
    hilo2(v.z, v.w, h23, l23);
    reinterpret_cast<uint2*>(g_xh)[i] = make_uint2(h01, h23);
    reinterpret_cast<uint2*>(g_xl)[i] = make_uint2(l01, l23);
}

__global__ void __launch_bounds__(256) prep_w(
    const float* __restrict__ Wq, const float* __restrict__ Wk,
    const float* __restrict__ Wv, const float* __restrict__ Wo)
{
    __shared__ float t[32][33];
    const int z = blockIdx.z;
    const float* W = (z == 0) ? Wq : (z == 1) ? Wk : (z == 2) ? Wv : Wo;
    const int n0 = blockIdx.x * 32, k0 = blockIdx.y * 32;
    const int tx = threadIdx.x & 31, ty = threadIdx.x >> 5;
#pragma unroll
    for (int i = 0; i < 4; i++)
        t[ty + 8 * i][tx] = W[(size_t)(k0 + ty + 8 * i) * DMODEL + n0 + tx];
    __syncthreads();
    const size_t base = (size_t)z * DMODEL * DMODEL;
#pragma unroll
    for (int i = 0; i < 4; i++) {
        const int r = ty + 8 * i;
        const float v = t[tx][r];                  // W[k0+tx][n0+r]
        const __nv_bfloat16 h = __float2bfloat16(v);
        const __nv_bfloat16 l = __float2bfloat16(v - __bfloat162float(h));
        g_WTh[base + (size_t)(n0 + r) * DMODEL + k0 + tx] = h;
        g_WTl[base + (size_t)(n0 + r) * DMODEL + k0 + tx] = l;
    }
}

// ============================================================================
// GEMM v3: pre-split bf16 hi/lo, pure cp.async, K-chunk 32, 2 CTAs/SM.
// D = A @ WT^T + bias.  A,B both K-major [row][k], ASTR=40 tiles (R8-proven).
// MODE 1: A=xh/xl, z=blockIdx.z in {0,1,2} -> Q/K/V hi/lo head-major (scl)
// MODE 0: A=Oh/Ol, z=3 -> fp32 token-major out
// ============================================================================
#define GSTR 40
#define GTILE_E (128 * GSTR)            // 5120 elems = 10240 B
#define GBUF_B (4 * GTILE_E * 2)        // 40960 B (Ah, Al, Bh, Bl)
#define GSMEM_BYTES (2 * GBUF_B)        // 81920 B

template <int MODE>
__global__ void __launch_bounds__(256, 2) gemm_ps(
    const float* __restrict__ b0, const float* __restrict__ b1,
    const float* __restrict__ b2, float* __restrict__ outp)
{
    extern __shared__ __nv_bfloat16 smb[];
    const unsigned sbase = sptr(smb);
    const int tid = threadIdx.x, lane = tid & 31, warp = tid >> 5;
    const int wm = (warp >> 1) * 32, wn = (warp & 1) * 64;
    const int m0 = blockIdx.y * 128, n0 = blockIdx.x * 128;
    const int z = (MODE == 1) ? blockIdx.z : 3;

    const __nv_bfloat16* Ahg = (MODE == 1) ? g_xh : g_Oh;
    const __nv_bfloat16* Alg = (MODE == 1) ? g_xl : g_Ol;
    const __nv_bfloat16* Bhg = g_WTh + (size_t)z * DMODEL * DMODEL;
    const __nv_bfloat16* Blg = g_WTl + (size_t)z * DMODEL * DMODEL;
    const float* bias = (MODE == 1) ? ((z == 0) ? b0 : (z == 1) ? b1 : b2) : b0;
    const float scl = (MODE == 1 && z == 0) ? 0.125f * LOG2E : 1.0f;

    auto stage = [&](int buf, int k0) {
        const unsigned bb = sbase + buf * GBUF_B;
#pragma unroll
        for (int j = 0; j < 2; j++) {
            const int idx = tid + j * 256;           // 0..511
            const int row = idx >> 2, ch = idx & 3;  // 128 rows x 4 chunks(8)
            const unsigned off = (row * GSTR + ch * 8) * 2;
            const size_t ga = (size_t)(m0 + row) * DMODEL + k0 + ch * 8;
            const size_t gb = (size_t)(n0 + row) * DMODEL + k0 + ch * 8;
            cpa16(bb + off,                   Ahg + ga);
            cpa16(bb + GTILE_E * 2 + off,     Alg + ga);
            cpa16(bb + 2 * GTILE_E * 2 + off, Bhg + gb);
            cpa16(bb + 3 * GTILE_E * 2 + off, Blg + gb);
        }
    };
    stage(0, 0);  cp_commit();
    stage(1, 32); cp_commit();

    float acc[2][8][4];
#pragma unroll
    for (int mt = 0; mt < 2; mt++)
#pragma unroll
        for (int nt = 0; nt < 8; nt++)
#pragma unroll
            for (int e = 0; e < 4; e++) acc[mt][nt][e] = 0.f;

    const int koff = (lane >> 4) << 3;
    for (int kt = 0; kt < 32; ++kt) {
        cp_wait<1>();
        __syncthreads();
        const unsigned bb = sbase + (kt & 1) * GBUF_B;

#pragma unroll
        for (int kk = 0; kk < 32; kk += 16) {
            unsigned afh[2][4], afl[2][4];
#pragma unroll
            for (int mt = 0; mt < 2; mt++) {
                const unsigned sa = bb +
                    ((wm + mt * 16 + (lane & 15)) * GSTR + kk + koff) * 2;
                ldsm_x4(afh[mt], sa);
                ldsm_x4(afl[mt], sa + GTILE_E * 2);
            }
#pragma unroll
            for (int p = 0; p < 4; p++) {
                unsigned rh[4], rl[4];
                const unsigned sb = bb + 2 * GTILE_E * 2 +
                    ((wn + p * 16 + (lane & 15)) * GSTR + kk + koff) * 2;
                ldsm_x4(rh, sb);
                ldsm_x4(rl, sb + GTILE_E * 2);
                unsigned bh0[2] = {rh[0], rh[2]}, bh1[2] = {rh[1], rh[3]};
                unsigned bl0[2] = {rl[0], rl[2]}, bl1[2] = {rl[1], rl[3]};
#pragma unroll
                for (int mt = 0; mt < 2; mt++) {
                    mma_bf16(acc[mt][2 * p],     afh[mt], bh0);
                    mma_bf16(acc[mt][2 * p],     afh[mt], bl0);
                    mma_bf16(acc[mt][2 * p],     afl[mt], bh0);
                    mma_bf16(acc[mt][2 * p + 1], afh[mt], bh1);
                    mma_bf16(acc[mt][2 * p + 1], afh[mt], bl1);
                    mma_bf16(acc[mt][2 * p + 1], afl[mt], bh1);
                }
            }
        }

        __syncthreads();
        if (kt + 2 < 32) stage(kt & 1, (kt + 2) * 32);
        cp_commit();
    }

#pragma unroll
    for (int mt = 0; mt < 2; mt++) {
        const int r0 = m0 + wm + mt * 16 + (lane >> 2);
#pragma unroll
        for (int nt = 0; nt < 8; nt++) {
            const int c = n0 + wn + nt * 8 + ((lane & 3) << 1);
            const float b0v = bias[c], b1v = bias[c + 1];
            const float v00 = acc[mt][nt][0] + b0v;
            const float v01 = acc[mt][nt][1] + b1v;
            const float v10 = acc[mt][nt][2] + b0v;
            const float v11 = acc[mt][nt][3] + b1v;
            if (MODE == 0) {
                *(float2*)&outp[(size_t)r0 * DMODEL + c]       = make_float2(v00, v01);
                *(float2*)&outp[(size_t)(r0 + 8) * DMODEL + c] = make_float2(v10, v11);
            } else {
                const int s = r0 & 2047;
                const int h = c >> 6, d = c & 63;
                const int bh = (r0 >> 11) * NHEADS + h;
                unsigned hi0, lo0, hi1, lo1;
                hilo2(v00 * scl, v01 * scl, hi0, lo0);
                hilo2(v10 * scl, v11 * scl, hi1, lo1);
                __nv_bfloat16* dh = (z == 0) ? g_Qh : (z == 1) ? g_Kh : g_Vh;
                __nv_bfloat16* dl = (z == 0) ? g_Ql : (z == 1) ? g_Kl : g_Vl;
                const size_t i0 = ((size_t)bh * S_LEN + s) * DK + d;
                const size_t i1 = ((size_t)bh * S_LEN + s + 8) * DK + d;
                *(unsigned*)&dh[i0] = hi0;  *(unsigned*)&dl[i0] = lo0;
                *(unsigned*)&dh[i1] = hi1;  *(unsigned*)&dl[i1] = lo1;
            }
        }
    }
}

// ============================ phase kernel ============================
#define WPT_STRIDE 1032
#define PHASE_SMEM_BYTES (16 * WPT_STRIDE * 4)

__global__ void __launch_bounds__(256) phase_kernel3(
    const float* __restrict__ x, const float* __restrict__ Wp,
    const float* __restrict__ bp, float* __restrict__ cs, float* __restrict__ sn)
{
    extern __shared__ float WpT[];
    const int tid = threadIdx.x;
    for (int idx = tid; idx < DMODEL * NHEADS; idx += 256) {
        const int k = idx >> 4, h = idx & 15;
        WpT[h * WPT_STRIDE + k] = Wp[idx];
    }
    __syncthreads();

    const int lane = tid & 31;
    const int warp = tid >> 5;
    const int t0 = blockIdx.x * 16 + warp * 2;

    float a0[NHEADS], a1[NHEADS];
#pragma unroll
    for (int h = 0; h < NHEADS; h++) { a0[h] = 0.f; a1[h] = 0.f; }
#pragma unroll 4
    for (int i = 0; i < 32; ++i) {
        const int k = i * 32 + lane;
        const float x0 = x[(size_t)t0 * DMODEL + k];
        const float x1 = x[(size_t)(t0 + 1) * DMODEL + k];
#pragma unroll
        for (int h = 0; h < NHEADS; h++) {
            const float w = WpT[h * WPT_STRIDE + k];
            a0[h] = fmaf(x0, w, a0[h]);
            a1[h] = fmaf(x1, w, a1[h]);
        }
    }
    float p0 = 0.f, p1 = 0.f;
#pragma unroll
    for (int h = 0; h < NHEADS; h++) {
        float v0 = a0[h], v1 = a1[h];
#pragma unroll
        for (int off = 16; off >= 1; off >>= 1) {
            v0 += __shfl_xor_sync(0xffffffffu, v0, off);
            v1 += __shfl_xor_sync(0xffffffffu, v1, off);
        }
        if (lane == h) { p0 = v0; p1 = v1; }
    }
    if (lane < NHEADS) {
        const float bpl = bp[lane];
#pragma unroll
        for (int u = 0; u < 2; u++) {
            const int t = t0 + u;
            const int bh = (t >> 11) * NHEADS + lane;
            float sv, cv;
            sincosf((u ? p1 : p0) + bpl, &sv, &cv);
            cs[bh * S_LEN + (t & 2047)] = cv;
            sn[bh * S_LEN + (t & 2047)] = sv;
        }
    }
}

// ============================ attention (R8 geometry + exp2) ============================
#define TSTR   72
#define TILE_E (128 * TSTR)
#define BUF0   (2 * TILE_E)
#define BUF_BLK (4 * TILE_E)
#define KC_BYTE_OFF ((2 * TILE_E + 2 * BUF_BLK) * 2)
#define ATT_SMEM_BYTES (KC_BYTE_OFF + 4 * 128 * 4)

__global__ void __launch_bounds__(256, 1) attn_mma(
    const float* __restrict__ cs, const float* __restrict__ sn,
    const float* __restrict__ alpha)
{
    extern __shared__ __nv_bfloat16 smb[];
    const unsigned sbase = sptr(smb);
    const int tid  = threadIdx.x;
    const int lane = tid & 31;
    const int warp = tid >> 5;
    const int bh = blockIdx.y;
    const int q0 = blockIdx.x * 128;

    {
        const __nv_bfloat16* qsrc[2] = {g_Qh, g_Ql};
#pragma unroll
        for (int t = 0; t < 2; t++)
#pragma unroll
            for (int j = 0; j < 4; j++) {
                const int idx = tid + j * 256;
                const int row = idx >> 3, ch = idx & 7;
                cpa16(sbase + (t * TILE_E + row * TSTR + ch * 8) * 2,
                      qsrc[t] + ((size_t)(bh * S_LEN + q0 + row) * DK + ch * 8));
            }
    }
    const __nv_bfloat16* kvsrc[4] = {g_Kh, g_Kl, g_Vh, g_Vl};
#pragma unroll 1
    for (int pre = 0; pre < 2; pre++) {
        const int c0 = pre * 128;
#pragma unroll
        for (int t = 0; t < 4; t++) {
            const unsigned dbase = sbase + (BUF0 + pre * BUF_BLK + t * TILE_E) * 2;
#pragma unroll
            for (int j = 0; j < 4; j++) {
                const int idx = tid + j * 256;
                const int row = idx >> 3, ch = idx & 7;
                cpa16(dbase + (row * TSTR + ch * 8) * 2,
                      kvsrc[t] + ((size_t)(bh * S_LEN + c0 + row) * DK + ch * 8));
            }
        }
        if (tid < 64) {
            const int arr = tid >> 5, q = tid & 31;
            const float* s = arr ? sn : cs;
            cpa16(sbase + KC_BYTE_OFF + pre * 1024 + arr * 512 + q * 16,
                  s + (size_t)bh * S_LEN + c0 + q * 4);
        }
        cp_commit();
    }

    const float alp = alpha[bh & (NHEADS - 1)] * LOG2E;
    const int rq_lo = q0 + warp * 16 + (lane >> 2);
    const float aqc_lo = alp * cs[bh * S_LEN + rq_lo];
    const float aqs_lo = alp * sn[bh * S_LEN + rq_lo];
    const float aqc_hi = alp * cs[bh * S_LEN + rq_lo + 8];
    const float aqs_hi = alp * sn[bh * S_LEN + rq_lo + 8];

    cp_wait<1>();
    __syncthreads();

    const int koff = (lane >> 4) << 3;
    unsigned afh[4][4], afl[4][4];
#pragma unroll
    for (int ks = 0; ks < 4; ks++) {
        const unsigned sa = sbase +
            ((warp * 16 + (lane & 15)) * TSTR + ks * 16 + koff) * 2;
        ldsm_x4(afh[ks], sa);
        ldsm_x4(afl[ks], sa + TILE_E * 2);
    }

    float m_lo = -1e30f, m_hi = -1e30f, l_lo = 0.f, l_hi = 0.f;
    float o[8][4];
#pragma unroll
    for (int nt = 0; nt < 8; nt++)
#pragma unroll
        for (int e = 0; e < 4; e++) o[nt][e] = 0.f;

    const float* fkc = (const float*)((const char*)smb + KC_BYTE_OFF);

    for (int kt = 0; kt < S_LEN / 128; ++kt) {
        if (kt) { cp_wait<1>(); __syncthreads(); }
        const int buf = kt & 1;
        const unsigned kb = sbase + (BUF0 + buf * BUF_BLK) * 2;

        float acc[16][4];
#pragma unroll
        for (int t = 0; t < 16; t++)
#pragma unroll
            for (int e = 0; e < 4; e++) acc[t][e] = 0.f;

#pragma unroll
        for (int ks = 0; ks < 4; ks++) {
#pragma unroll
            for (int p = 0; p < 8; p++) {
                unsigned rh[4], rl[4];
                const unsigned ka = kb +
                    ((p * 16 + (lane & 15)) * TSTR + ks * 16 + koff) * 2;
                ldsm_x4(rh, ka);
                ldsm_x4(rl, ka + TILE_E * 2);
                unsigned bh0[2] = {rh[0], rh[2]}, bh1[2] = {rh[1], rh[3]};
                unsigned bl0[2] = {rl[0], rl[2]}, bl1[2] = {rl[1], rl[3]};
                mma_bf16(acc[2 * p],     afh[ks], bh0);
                mma_bf16(acc[2 * p],     afh[ks], bl0);
                mma_bf16(acc[2 * p],     afl[ks], bh0);
                mma_bf16(acc[2 * p + 1], afh[ks], bh1);
                mma_bf16(acc[2 * p + 1], afh[ks], bl1);
                mma_bf16(acc[2 * p + 1], afl[ks], bh1);
            }
        }

        const float* kcb = fkc + buf * 256;
        float mx_lo = -1e30f, mx_hi = -1e30f;
#pragma unroll
        for (int t = 0; t < 16; t++) {
            const float2 kc2 = *(const float2*)&kcb[t * 8 + ((lane & 3) << 1)];
            const float2 ks2 = *(const float2*)&kcb[128 + t * 8 + ((lane & 3) << 1)];
            acc[t][0] += aqc_lo * kc2.x + aqs_lo * ks2.x;
            acc[t][1] += aqc_lo * kc2.y + aqs_lo * ks2.y;
            acc[t][2] += aqc_hi * kc2.x + aqs_hi * ks2.x;
            acc[t][3] += aqc_hi * kc2.y + aqs_hi * ks2.y;
            mx_lo = fmaxf(mx_lo, fmaxf(acc[t][0], acc[t][1]));
            mx_hi = fmaxf(mx_hi, fmaxf(acc[t][2], acc[t][3]));
        }
        mx_lo = fmaxf(mx_lo, __shfl_xor_sync(0xffffffffu, mx_lo, 1));
        mx_lo = fmaxf(mx_lo, __shfl_xor_sync(0xffffffffu, mx_lo, 2));
        mx_hi = fmaxf(mx_hi, __shfl_xor_sync(0xffffffffu, mx_hi, 1));
        mx_hi = fmaxf(mx_hi, __shfl_xor_sync(0xffffffffu, mx_hi, 2));

        const float mn_lo = fmaxf(m_lo, mx_lo);
        const float mn_hi = fmaxf(m_hi, mx_hi);
        const float cr_lo = ex2(m_lo - mn_lo);
        const float cr_hi = ex2(m_hi - mn_hi);
        m_lo = mn_lo; m_hi = mn_hi;

        float sum_lo = 0.f, sum_hi = 0.f;
#pragma unroll
        for (int t = 0; t < 16; t++) {
            acc[t][0] = ex2(acc[t][0] - m_lo); sum_lo += acc[t][0];
            acc[t][1] = ex2(acc[t][1] - m_lo); sum_lo += acc[t][1];
            acc[t][2] = ex2(acc[t][2] - m_hi); sum_hi += acc[t][2];
            acc[t][3] = ex2(acc[t][3] - m_hi); sum_hi += acc[t][3];
        }
        sum_lo += __shfl_xor_sync(0xffffffffu, sum_lo, 1);
        sum_lo += __shfl_xor_sync(0xffffffffu, sum_lo, 2);
        sum_hi += __shfl_xor_sync(0xffffffffu, sum_hi, 1);
        sum_hi += __shfl_xor_sync(0xffffffffu, sum_hi, 2);
        l_lo = l_lo * cr_lo + sum_lo;
        l_hi = l_hi * cr_hi + sum_hi;

#pragma unroll
        for (int nt = 0; nt < 8; nt++) {
            o[nt][0] *= cr_lo; o[nt][1] *= cr_lo;
            o[nt][2] *= cr_hi; o[nt][3] *= cr_hi;
        }

        // PV: P hi/lo 3-term x V hi/lo
        const unsigned vb = kb + 2 * TILE_E * 2;
#pragma unroll
        for (int t2 = 0; t2 < 8; t2++) {
            unsigned aPh[4], aPl[4];
            hilo2(acc[2 * t2][0],     acc[2 * t2][1],     aPh[0], aPl[0]);
            hilo2(acc[2 * t2][2],     acc[2 * t2][3],     aPh[1], aPl[1]);
            hilo2(acc[2 * t2 + 1][0], acc[2 * t2 + 1][1], aPh[2], aPl[2]);
            hilo2(acc[2 * t2 + 1][2], acc[2 * t2 + 1][3], aPh[3], aPl[3]);
#pragma unroll
            for (int dp = 0; dp < 4; dp++) {
                unsigned rh[4], rl[4];
                const unsigned va = vb +
                    ((t2 * 16 + (lane & 15)) * TSTR + dp * 16 + koff) * 2;
                ldsm_x4t(rh, va);
                ldsm_x4t(rl, va + TILE_E * 2);
                unsigned bh0[2] = {rh[0], rh[1]}, bh1[2] = {rh[2], rh[3]};
                unsigned bl0[2] = {rl[0], rl[1]}, bl1[2] = {rl[2], rl[3]};
                mma_bf16(o[2 * dp],     aPh, bh0);
                mma_bf16(o[2 * dp],     aPh, bl0);
                mma_bf16(o[2 * dp],     aPl, bh0);
                mma_bf16(o[2 * dp + 1], aPh, bh1);
                mma_bf16(o[2 * dp + 1], aPh, bl1);
                mma_bf16(o[2 * dp + 1], aPl, bh1);
            }
        }

        __syncthreads();
        if (kt + 2 < S_LEN / 128) {
            const int c0 = (kt + 2) * 128;
#pragma unroll
            for (int t = 0; t < 4; t++) {
                const unsigned dbase = sbase + (BUF0 + buf * BUF_BLK + t * TILE_E) * 2;
#pragma unroll
                for (int j = 0; j < 4; j++) {
                    const int idx = tid + j * 256;
                    const int row = idx >> 3, ch = idx & 7;
                    cpa16(dbase + (row * TSTR + ch * 8) * 2,
                          kvsrc[t] + ((size_t)(bh * S_LEN + c0 + row) * DK + ch * 8));
                }
            }
            if (tid < 64) {
                const int arr = tid >> 5, q = tid & 31;
                const float* s = arr ? sn : cs;
                cpa16(sbase + KC_BYTE_OFF + buf * 1024 + arr * 512 + q * 16,
                      s + (size_t)bh * S_LEN + c0 + q * 4);
            }
        }
        cp_commit();
    }

    // epilogue: bf16 hi/lo token-major (pre-split for output projection)
    const int b = bh >> 4, h = bh & 15;
    const float inv_lo = 1.f / l_lo;
    const float inv_hi = 1.f / l_hi;
    const int row_lo = q0 + warp * 16 + (lane >> 2);
#pragma unroll
    for (int nt = 0; nt < 8; nt++) {
        const int col = h * DK + nt * 8 + ((lane & 3) << 1);
        unsigned hi, lo;
        hilo2(o[nt][0] * inv_lo, o[nt][1] * inv_lo, hi, lo);
        const size_t i0 = ((size_t)b * S_LEN + row_lo) * DMODEL + col;
        *(unsigned*)&g_Oh[i0] = hi;
        *(unsigned*)&g_Ol[i0] = lo;
        hilo2(o[nt][2] * inv_hi, o[nt][3] * inv_hi, hi, lo);
        const size_t i1 = ((size_t)b * S_LEN + row_lo + 8) * DMODEL + col;
        *(unsigned*)&g_Oh[i1] = hi;
        *(unsigned*)&g_Ol[i1] = lo;
    }
}

// ============================================================================
extern "C" void kernel_launch(void* const* d_in, const int* in_sizes, int n_in,
                              void* d_out, int out_size)
{
    const float* x     = (const float*)d_in[0];
    const float* Wq    = (const float*)d_in[1];
    const float* bq    = (const float*)d_in[2];
    const float* Wk    = (const float*)d_in[3];
    const float* bk    = (const float*)d_in[4];
    const float* Wv    = (const float*)d_in[5];
    const float* bv    = (const float*)d_in[6];
    const float* Wo    = (const float*)d_in[7];
    const float* bo    = (const float*)d_in[8];
    const float* Wp    = (const float*)d_in[9];
    const float* bp    = (const float*)d_in[10];
    const float* alpha = (const float*)d_in[11];
    float* out = (float*)d_out;

    float *pc, *ps;
    cudaGetSymbolAddress((void**)&pc, g_cs);
    cudaGetSymbolAddress((void**)&ps, g_sn);

    cudaFuncSetAttribute(gemm_ps<0>, cudaFuncAttributeMaxDynamicSharedMemorySize, GSMEM_BYTES);
    cudaFuncSetAttribute(gemm_ps<1>, cudaFuncAttributeMaxDynamicSharedMemorySize, GSMEM_BYTES);
    cudaFuncSetAttribute(phase_kernel3, cudaFuncAttributeMaxDynamicSharedMemorySize, PHASE_SMEM_BYTES);
    cudaFuncSetAttribute(attn_mma, cudaFuncAttributeMaxDynamicSharedMemorySize, ATT_SMEM_BYTES);

    prep_x<<<NTOK * DMODEL / 1024, 256>>>(x);
    prep_w<<<dim3(32, 32, 4), 256>>>(Wq, Wk, Wv, Wo);
    phase_kernel3<<<NTOK / 16, 256, PHASE_SMEM_BYTES>>>(x, Wp, bp, pc, ps);

    gemm_ps<1><<<dim3(8, 32, 3), 256, GSMEM_BYTES>>>(bq, bk, bv, nullptr);

    attn_mma<<<dim3(S_LEN / 128, BHALL), 256, ATT_SMEM_BYTES>>>(pc, ps, alpha);

    gemm_ps<0><<<dim3(8, 32, 1), 256, GSMEM_BYTES>>>(bo, nullptr, nullptr, out);
}

// round 14
// speedup vs baseline: 1.4108x; 1.4108x over previous
#include <cuda_runtime.h>
#include <cuda_bf16.h>
#include <cuda_fp16.h>
#include <math.h>
#include <stdint.h>

#define S_LEN   2048
#define DMODEL  1024
#define NHEADS  16
#define DK      64
#define BATCH   2
#define NTOK    (BATCH * S_LEN)
#define BHALL   (BATCH * NHEADS)
#define LOG2E   1.44269504f

__device__ __align__(256) __half g_Qf[BHALL * S_LEN * DK];
__device__ __align__(256) __half g_Kf[BHALL * S_LEN * DK];
__device__ __align__(256) __half g_Vf[BHALL * S_LEN * DK];
__device__ float g_O[NTOK * DMODEL];
__device__ float g_cs[BHALL * S_LEN];
__device__ float g_sn[BHALL * S_LEN];

// ============================ helpers ============================
__device__ __forceinline__ unsigned sptr(const void* p) {
    return (unsigned)__cvta_generic_to_shared(p);
}
__device__ __forceinline__ void ldsm_x4(unsigned r[4], unsigned sa) {
    asm volatile("ldmatrix.sync.aligned.m8n8.x4.shared.b16 {%0,%1,%2,%3}, [%4];"
                 : "=r"(r[0]), "=r"(r[1]), "=r"(r[2]), "=r"(r[3]) : "r"(sa));
}
__device__ __forceinline__ void ldsm_x4t(unsigned r[4], unsigned sa) {
    asm volatile("ldmatrix.sync.aligned.m8n8.x4.trans.shared.b16 {%0,%1,%2,%3}, [%4];"
                 : "=r"(r[0]), "=r"(r[1]), "=r"(r[2]), "=r"(r[3]) : "r"(sa));
}
__device__ __forceinline__ void mma_bf16(float c[4], const unsigned a[4], const unsigned b[2]) {
    asm volatile(
        "mma.sync.aligned.m16n8k16.row.col.f32.bf16.bf16.f32 "
        "{%0,%1,%2,%3}, {%4,%5,%6,%7}, {%8,%9}, {%0,%1,%2,%3};"
        : "+f"(c[0]), "+f"(c[1]), "+f"(c[2]), "+f"(c[3])
        : "r"(a[0]), "r"(a[1]), "r"(a[2]), "r"(a[3]), "r"(b[0]), "r"(b[1]));
}
__device__ __forceinline__ void mma_f16(float c[4], const unsigned a[4], const unsigned b[2]) {
    asm volatile(
        "mma.sync.aligned.m16n8k16.row.col.f32.f16.f16.f32 "
        "{%0,%1,%2,%3}, {%4,%5,%6,%7}, {%8,%9}, {%0,%1,%2,%3};"
        : "+f"(c[0]), "+f"(c[1]), "+f"(c[2]), "+f"(c[3])
        : "r"(a[0]), "r"(a[1]), "r"(a[2]), "r"(a[3]), "r"(b[0]), "r"(b[1]));
}
__device__ __forceinline__ void cpa16(unsigned d, const void* s) {
    asm volatile("cp.async.cg.shared.global [%0], [%1], 16;" :: "r"(d), "l"(s));
}
__device__ __forceinline__ void cp_commit() { asm volatile("cp.async.commit_group;"); }
template <int N> __device__ __forceinline__ void cp_wait() {
    asm volatile("cp.async.wait_group %0;" :: "n"(N));
}
__device__ __forceinline__ unsigned packbf(float e0, float e1) {
    unsigned r;
    asm("cvt.rn.bf16x2.f32 %0, %1, %2;" : "=r"(r) : "f"(e1), "f"(e0));
    return r;
}
__device__ __forceinline__ void hilo2(float e0, float e1, unsigned& hi, unsigned& lo) {
    hi = packbf(e0, e1);
    const float f0 = __uint_as_float(hi << 16);
    const float f1 = __uint_as_float(hi & 0xffff0000u);
    lo = packbf(e0 - f0, e1 - f1);
}
__device__ __forceinline__ void f4_to_hilo(const float4 v,
    unsigned& h01, unsigned& h23, unsigned& l01, unsigned& l23)
{
    hilo2(v.x, v.y, h01, l01);
    hilo2(v.z, v.w, h23, l23);
}
__device__ __forceinline__ unsigned packh2(float e0, float e1) {
    const __half2 h = __floats2half2_rn(e0, e1);
    return *reinterpret_cast<const unsigned*>(&h);
}
__device__ __forceinline__ float ex2(float x) {
    float r;
    asm("ex2.approx.f32 %0, %1;" : "=f"(r) : "f"(x));
    return r;
}

// ============================================================================
// GEMM (R8-proven): fused fp32->bf16 hi/lo convert in staging, K-chunk 32,
// 3-term bf16 split (error ~2e-5).
// MODE 0: fp32 C[m*N+n].  MODE 1: __half head-major Cf[(bh*S+s)*64+d] * scl.
// ============================================================================
#define ASTR 40
#define BSTR 136
#define A_ELEMS (128 * ASTR)
#define B_ELEMS (32 * BSTR)
#define BUF_ELEMS (2 * A_ELEMS + 2 * B_ELEMS)
#define MMA_SMEM_BYTES (2 * BUF_ELEMS * 2)

template <int MODE>
__global__ void __launch_bounds__(256) gemm_mma(
    const float* __restrict__ A, const float* __restrict__ B,
    const float* __restrict__ bias, float* __restrict__ C,
    __half* __restrict__ Cf, float scl, int M, int N, int K)
{
    extern __shared__ __nv_bfloat16 smb[];
    const int tid  = threadIdx.x;
    const int lane = tid & 31;
    const int warp = tid >> 5;
    const int wm = (warp >> 1) * 32;
    const int wn = (warp & 1) * 64;
    const int m0 = blockIdx.y * 128;
    const int n0 = blockIdx.x * 128;

    int arow[4], acol[4], brow[4], bcol[4];
#pragma unroll
    for (int j = 0; j < 4; j++) {
        const int idx = tid + j * 256;
        arow[j] = idx >> 3;  acol[j] = (idx & 7) << 2;
        brow[j] = idx >> 5;  bcol[j] = (idx & 31) << 2;
    }

    float4 pa[4], pb[4];
#pragma unroll
    for (int j = 0; j < 4; j++) {
        pa[j] = *(const float4*)&A[(size_t)(m0 + arow[j]) * K + acol[j]];
        pb[j] = *(const float4*)&B[(size_t)brow[j] * N + n0 + bcol[j]];
    }
    {
        __nv_bfloat16* Ah = smb;
        __nv_bfloat16* Al = Ah + A_ELEMS;
        __nv_bfloat16* Bh = smb + 2 * A_ELEMS;
        __nv_bfloat16* Bl = Bh + B_ELEMS;
#pragma unroll
        for (int j = 0; j < 4; j++) {
            unsigned h01, h23, l01, l23;
            f4_to_hilo(pa[j], h01, h23, l01, l23);
            *reinterpret_cast<uint2*>(&Ah[arow[j] * ASTR + acol[j]]) = make_uint2(h01, h23);
            *reinterpret_cast<uint2*>(&Al[arow[j] * ASTR + acol[j]]) = make_uint2(l01, l23);
            f4_to_hilo(pb[j], h01, h23, l01, l23);
            *reinterpret_cast<uint2*>(&Bh[brow[j] * BSTR + bcol[j]]) = make_uint2(h01, h23);
            *reinterpret_cast<uint2*>(&Bl[brow[j] * BSTR + bcol[j]]) = make_uint2(l01, l23);
        }
    }
    __syncthreads();

    float acc[2][8][4];
#pragma unroll
    for (int mt = 0; mt < 2; mt++)
#pragma unroll
        for (int nt = 0; nt < 8; nt++)
#pragma unroll
            for (int e = 0; e < 4; e++) acc[mt][nt][e] = 0.f;

    const int KT = K / 32;
    for (int kt = 0; kt < KT; ++kt) {
        const int buf = kt & 1;
        if (kt + 1 < KT) {
            const int k0 = (kt + 1) * 32;
#pragma unroll
            for (int j = 0; j < 4; j++) {
                pa[j] = *(const float4*)&A[(size_t)(m0 + arow[j]) * K + k0 + acol[j]];
                pb[j] = *(const float4*)&B[(size_t)(k0 + brow[j]) * N + n0 + bcol[j]];
            }
        }

        const __nv_bfloat16* Ah = smb + buf * BUF_ELEMS;
        const __nv_bfloat16* Bh = smb + buf * BUF_ELEMS + 2 * A_ELEMS;

#pragma unroll
        for (int kk = 0; kk < 32; kk += 16) {
            unsigned afh[2][4], afl[2][4];
#pragma unroll
            for (int mt = 0; mt < 2; mt++) {
                unsigned sa = sptr(&Ah[(wm + mt * 16 + (lane & 15)) * ASTR
                                       + kk + ((lane >> 4) << 3)]);
                ldsm_x4(afh[mt], sa);
                ldsm_x4(afl[mt], sa + A_ELEMS * 2);
            }
            unsigned bfh[8][2], bfl[8][2];
#pragma unroll
            for (int np = 0; np < 4; np++) {
                unsigned sb = sptr(&Bh[(kk + (lane & 15)) * BSTR
                                       + wn + np * 16 + ((lane >> 4) << 3)]);
                unsigned r[4];
                ldsm_x4t(r, sb);
                bfh[2 * np][0] = r[0]; bfh[2 * np][1] = r[1];
                bfh[2 * np + 1][0] = r[2]; bfh[2 * np + 1][1] = r[3];
                ldsm_x4t(r, sb + B_ELEMS * 2);
                bfl[2 * np][0] = r[0]; bfl[2 * np][1] = r[1];
                bfl[2 * np + 1][0] = r[2]; bfl[2 * np + 1][1] = r[3];
            }
#pragma unroll
            for (int mt = 0; mt < 2; mt++)
#pragma unroll
                for (int nt = 0; nt < 8; nt++) {
                    mma_bf16(acc[mt][nt], afh[mt], bfh[nt]);
                    mma_bf16(acc[mt][nt], afh[mt], bfl[nt]);
                    mma_bf16(acc[mt][nt], afl[mt], bfh[nt]);
                }
        }

        if (kt + 1 < KT) {
            const int nb = 1 - buf;
            __nv_bfloat16* nAh = smb + nb * BUF_ELEMS;
            __nv_bfloat16* nAl = nAh + A_ELEMS;
            __nv_bfloat16* nBh = smb + nb * BUF_ELEMS + 2 * A_ELEMS;
            __nv_bfloat16* nBl = nBh + B_ELEMS;
#pragma unroll
            for (int j = 0; j < 4; j++) {
                unsigned h01, h23, l01, l23;
                f4_to_hilo(pa[j], h01, h23, l01, l23);
                *reinterpret_cast<uint2*>(&nAh[arow[j] * ASTR + acol[j]]) = make_uint2(h01, h23);
                *reinterpret_cast<uint2*>(&nAl[arow[j] * ASTR + acol[j]]) = make_uint2(l01, l23);
                f4_to_hilo(pb[j], h01, h23, l01, l23);
                *reinterpret_cast<uint2*>(&nBh[brow[j] * BSTR + bcol[j]]) = make_uint2(h01, h23);
                *reinterpret_cast<uint2*>(&nBl[brow[j] * BSTR + bcol[j]]) = make_uint2(l01, l23);
            }
            __syncthreads();
        }
    }

#pragma unroll
    for (int mt = 0; mt < 2; mt++) {
        const int r0 = m0 + wm + mt * 16 + (lane >> 2);
#pragma unroll
        for (int nt = 0; nt < 8; nt++) {
            const int c = n0 + wn + nt * 8 + ((lane & 3) << 1);
            const float b0v = bias[c], b1v = bias[c + 1];
            const float v00 = acc[mt][nt][0] + b0v;
            const float v01 = acc[mt][nt][1] + b1v;
            const float v10 = acc[mt][nt][2] + b0v;
            const float v11 = acc[mt][nt][3] + b1v;
            if (MODE == 0) {
                *(float2*)&C[(size_t)r0 * N + c]       = make_float2(v00, v01);
                *(float2*)&C[(size_t)(r0 + 8) * N + c] = make_float2(v10, v11);
            } else {
                const int s = r0 & 2047;
                const int h = c >> 6, d = c & 63;
                const int bh = (r0 >> 11) * NHEADS + h;
                const size_t i0 = ((size_t)bh * S_LEN + s) * DK + d;
                const size_t i1 = ((size_t)bh * S_LEN + s + 8) * DK + d;
                *(unsigned*)&Cf[i0] = packh2(v00 * scl, v01 * scl);
                *(unsigned*)&Cf[i1] = packh2(v10 * scl, v11 * scl);
            }
        }
    }
}

// ============================ phase kernel ============================
#define WPT_STRIDE 1032
#define PHASE_SMEM_BYTES (16 * WPT_STRIDE * 4)

__global__ void __launch_bounds__(256) phase_kernel3(
    const float* __restrict__ x, const float* __restrict__ Wp,
    const float* __restrict__ bp, float* __restrict__ cs, float* __restrict__ sn)
{
    extern __shared__ float WpT[];
    const int tid = threadIdx.x;
    for (int idx = tid; idx < DMODEL * NHEADS; idx += 256) {
        const int k = idx >> 4, h = idx & 15;
        WpT[h * WPT_STRIDE + k] = Wp[idx];
    }
    __syncthreads();

    const int lane = tid & 31;
    const int warp = tid >> 5;
    const int t0 = blockIdx.x * 16 + warp * 2;

    float a0[NHEADS], a1[NHEADS];
#pragma unroll
    for (int h = 0; h < NHEADS; h++) { a0[h] = 0.f; a1[h] = 0.f; }
#pragma unroll 4
    for (int i = 0; i < 32; ++i) {
        const int k = i * 32 + lane;
        const float x0 = x[(size_t)t0 * DMODEL + k];
        const float x1 = x[(size_t)(t0 + 1) * DMODEL + k];
#pragma unroll
        for (int h = 0; h < NHEADS; h++) {
            const float w = WpT[h * WPT_STRIDE + k];
            a0[h] = fmaf(x0, w, a0[h]);
            a1[h] = fmaf(x1, w, a1[h]);
        }
    }
    float p0 = 0.f, p1 = 0.f;
#pragma unroll
    for (int h = 0; h < NHEADS; h++) {
        float v0 = a0[h], v1 = a1[h];
#pragma unroll
        for (int off = 16; off >= 1; off >>= 1) {
            v0 += __shfl_xor_sync(0xffffffffu, v0, off);
            v1 += __shfl_xor_sync(0xffffffffu, v1, off);
        }
        if (lane == h) { p0 = v0; p1 = v1; }
    }
    if (lane < NHEADS) {
        const float bpl = bp[lane];
#pragma unroll
        for (int u = 0; u < 2; u++) {
            const int t = t0 + u;
            const int bh = (t >> 11) * NHEADS + lane;
            float sv, cv;
            sincosf((u ? p1 : p0) + bpl, &sv, &cv);
            cs[bh * S_LEN + (t & 2047)] = cv;
            sn[bh * S_LEN + (t & 2047)] = sv;
        }
    }
}

// ============================================================================
// Attention, single fp16 mma (1-term QK, 1-term PV). TQ=128 x TK=64,
// 8 warps, 2 CTAs/SM (56 KB smem), exp2 softmax, fp32 accumulators.
// ============================================================================
#define TSTR   72
#define QF_E   (128 * TSTR)            // 9216
#define KVT_E  (64 * TSTR)             // 4608
#define BUF0_E QF_E
#define BUFBLK_E (2 * KVT_E)           // K,V
#define KC_BYTE_OFF ((QF_E + 2 * BUFBLK_E) * 2)   // 55296
#define ATT_SMEM_BYTES (KC_BYTE_OFF + 2 * 128 * 4) // 56320

__global__ void __launch_bounds__(256, 2) attn_f16(
    const float* __restrict__ cs, const float* __restrict__ sn,
    const float* __restrict__ alpha, float* __restrict__ O)
{
    extern __shared__ __half smh[];
    const unsigned sbase = sptr(smh);
    const int tid  = threadIdx.x;
    const int lane = tid & 31;
    const int warp = tid >> 5;
    const int bh = blockIdx.y;
    const int q0 = blockIdx.x * 128;

    // Q stage (128 rows x 64 halves)
#pragma unroll
    for (int j = 0; j < 4; j++) {
        const int idx = tid + j * 256;
        const int row = idx >> 3, ch = idx & 7;
        cpa16(sbase + (row * TSTR + ch * 8) * 2,
              g_Qf + ((size_t)(bh * S_LEN + q0 + row) * DK + ch * 8));
    }
#pragma unroll 1
    for (int pre = 0; pre < 2; pre++) {
        const int c0 = pre * 64;
        const unsigned kb = sbase + (BUF0_E + pre * BUFBLK_E) * 2;
#pragma unroll
        for (int j = 0; j < 2; j++) {
            const int idx = tid + j * 256;      // 0..511
            const int row = idx >> 3, ch = idx & 7;
            const unsigned off = (row * TSTR + ch * 8) * 2;
            cpa16(kb + off,             g_Kf + ((size_t)(bh * S_LEN + c0 + row) * DK + ch * 8));
            cpa16(kb + KVT_E * 2 + off, g_Vf + ((size_t)(bh * S_LEN + c0 + row) * DK + ch * 8));
        }
        if (tid < 32) {
            const int arr = tid >> 4, q = tid & 15;
            const float* s = arr ? sn : cs;
            cpa16(sbase + KC_BYTE_OFF + pre * 512 + arr * 256 + q * 16,
                  s + (size_t)bh * S_LEN + c0 + q * 4);
        }
        cp_commit();
    }

    const float alp = alpha[bh & (NHEADS - 1)] * LOG2E;
    const int rq_lo = q0 + warp * 16 + (lane >> 2);
    const float aqc_lo = alp * cs[bh * S_LEN + rq_lo];
    const float aqs_lo = alp * sn[bh * S_LEN + rq_lo];
    const float aqc_hi = alp * cs[bh * S_LEN + rq_lo + 8];
    const float aqs_hi = alp * sn[bh * S_LEN + rq_lo + 8];

    cp_wait<1>();
    __syncthreads();

    const int koff = (lane >> 4) << 3;
    const unsigned qrow = (warp * 16 + (lane & 15)) * TSTR;
    unsigned afq[4][4];
#pragma unroll
    for (int ks = 0; ks < 4; ks++)
        ldsm_x4(afq[ks], sbase + (qrow + ks * 16 + koff) * 2);

    float m_lo = -1e30f, m_hi = -1e30f, l_lo = 0.f, l_hi = 0.f;
    float o[8][4];
#pragma unroll
    for (int nt = 0; nt < 8; nt++)
#pragma unroll
        for (int e = 0; e < 4; e++) o[nt][e] = 0.f;

    const float* fkc = (const float*)((const char*)smh + KC_BYTE_OFF);

    for (int kt = 0; kt < S_LEN / 64; ++kt) {
        if (kt) { cp_wait<1>(); __syncthreads(); }
        const int buf = kt & 1;
        const unsigned kb = sbase + (BUF0_E + buf * BUFBLK_E) * 2;

        // ---- QK^T (1-term fp16): S[16 x 64] per warp ----
        float acc[8][4];
#pragma unroll
        for (int t = 0; t < 8; t++)
#pragma unroll
            for (int e = 0; e < 4; e++) acc[t][e] = 0.f;

#pragma unroll
        for (int ks = 0; ks < 4; ks++) {
#pragma unroll
            for (int p = 0; p < 4; p++) {
                unsigned rh[4];
                ldsm_x4(rh, kb + ((p * 16 + (lane & 15)) * TSTR + ks * 16 + koff) * 2);
                unsigned b0[2] = {rh[0], rh[2]}, b1[2] = {rh[1], rh[3]};
                mma_f16(acc[2 * p],     afq[ks], b0);
                mma_f16(acc[2 * p + 1], afq[ks], b1);
            }
        }

        // ---- coherence + online softmax (base-2) ----
        const float* kcb = fkc + buf * 128;
        float mx_lo = -1e30f, mx_hi = -1e30f;
#pragma unroll
        for (int t = 0; t < 8; t++) {
            const float2 kc2 = *(const float2*)&kcb[t * 8 + ((lane & 3) << 1)];
            const float2 ks2 = *(const float2*)&kcb[64 + t * 8 + ((lane & 3) << 1)];
            acc[t][0] += aqc_lo * kc2.x + aqs_lo * ks2.x;
            acc[t][1] += aqc_lo * kc2.y + aqs_lo * ks2.y;
            acc[t][2] += aqc_hi * kc2.x + aqs_hi * ks2.x;
            acc[t][3] += aqc_hi * kc2.y + aqs_hi * ks2.y;
            mx_lo = fmaxf(mx_lo, fmaxf(acc[t][0], acc[t][1]));
            mx_hi = fmaxf(mx_hi, fmaxf(acc[t][2], acc[t][3]));
        }
        mx_lo = fmaxf(mx_lo, __shfl_xor_sync(0xffffffffu, mx_lo, 1));
        mx_lo = fmaxf(mx_lo, __shfl_xor_sync(0xffffffffu, mx_lo, 2));
        mx_hi = fmaxf(mx_hi, __shfl_xor_sync(0xffffffffu, mx_hi, 1));
        mx_hi = fmaxf(mx_hi, __shfl_xor_sync(0xffffffffu, mx_hi, 2));

        const float mn_lo = fmaxf(m_lo, mx_lo);
        const float mn_hi = fmaxf(m_hi, mx_hi);
        const float cr_lo = ex2(m_lo - mn_lo);
        const float cr_hi = ex2(m_hi - mn_hi);
        m_lo = mn_lo; m_hi = mn_hi;

        float sum_lo = 0.f, sum_hi = 0.f;
#pragma unroll
        for (int t = 0; t < 8; t++) {
            acc[t][0] = ex2(acc[t][0] - m_lo); sum_lo += acc[t][0];
            acc[t][1] = ex2(acc[t][1] - m_lo); sum_lo += acc[t][1];
            acc[t][2] = ex2(acc[t][2] - m_hi); sum_hi += acc[t][2];
            acc[t][3] = ex2(acc[t][3] - m_hi); sum_hi += acc[t][3];
        }
        sum_lo += __shfl_xor_sync(0xffffffffu, sum_lo, 1);
        sum_lo += __shfl_xor_sync(0xffffffffu, sum_lo, 2);
        sum_hi += __shfl_xor_sync(0xffffffffu, sum_hi, 1);
        sum_hi += __shfl_xor_sync(0xffffffffu, sum_hi, 2);
        l_lo = l_lo * cr_lo + sum_lo;
        l_hi = l_hi * cr_hi + sum_hi;

#pragma unroll
        for (int nt = 0; nt < 8; nt++) {
            o[nt][0] *= cr_lo; o[nt][1] *= cr_lo;
            o[nt][2] *= cr_hi; o[nt][3] *= cr_hi;
        }

        // ---- PV (1-term fp16): P[16x64] x V[64x64] ----
        const unsigned vb = kb + KVT_E * 2;
#pragma unroll
        for (int t2 = 0; t2 < 4; t2++) {
            unsigned aP[4];
            aP[0] = packh2(acc[2 * t2][0],     acc[2 * t2][1]);
            aP[1] = packh2(acc[2 * t2][2],     acc[2 * t2][3]);
            aP[2] = packh2(acc[2 * t2 + 1][0], acc[2 * t2 + 1][1]);
            aP[3] = packh2(acc[2 * t2 + 1][2], acc[2 * t2 + 1][3]);
#pragma unroll
            for (int dp = 0; dp < 4; dp++) {
                unsigned rh[4];
                ldsm_x4t(rh, vb + ((t2 * 16 + (lane & 15)) * TSTR + dp * 16 + koff) * 2);
                unsigned b0[2] = {rh[0], rh[1]}, b1[2] = {rh[2], rh[3]};
                mma_f16(o[2 * dp],     aP, b0);
                mma_f16(o[2 * dp + 1], aP, b1);
            }
        }

        __syncthreads();
        if (kt + 2 < S_LEN / 64) {
            const int c0 = (kt + 2) * 64;
            const unsigned nb = sbase + (BUF0_E + buf * BUFBLK_E) * 2;
#pragma unroll
            for (int j = 0; j < 2; j++) {
                const int idx = tid + j * 256;
                const int row = idx >> 3, ch = idx & 7;
                const unsigned off = (row * TSTR + ch * 8) * 2;
                cpa16(nb + off,             g_Kf + ((size_t)(bh * S_LEN + c0 + row) * DK + ch * 8));
                cpa16(nb + KVT_E * 2 + off, g_Vf + ((size_t)(bh * S_LEN + c0 + row) * DK + ch * 8));
            }
            if (tid < 32) {
                const int arr = tid >> 4, q = tid & 15;
                const float* s = arr ? sn : cs;
                cpa16(sbase + KC_BYTE_OFF + buf * 512 + arr * 256 + q * 16,
                      s + (size_t)bh * S_LEN + c0 + q * 4);
            }
        }
        cp_commit();
    }

    // ---- epilogue: fp32 token-major ----
    const int b = bh >> 4, h = bh & 15;
    const float inv_lo = 1.f / l_lo;
    const float inv_hi = 1.f / l_hi;
    const int row_lo = q0 + warp * 16 + (lane >> 2);
#pragma unroll
    for (int nt = 0; nt < 8; nt++) {
        const int col = h * DK + nt * 8 + ((lane & 3) << 1);
        *(float2*)&O[((size_t)b * S_LEN + row_lo) * DMODEL + col] =
            make_float2(o[nt][0] * inv_lo, o[nt][1] * inv_lo);
        *(float2*)&O[((size_t)b * S_LEN + row_lo + 8) * DMODEL + col] =
            make_float2(o[nt][2] * inv_hi, o[nt][3] * inv_hi);
    }
}

// ============================================================================
extern "C" void kernel_launch(void* const* d_in, const int* in_sizes, int n_in,
                              void* d_out, int out_size)
{
    const float* x     = (const float*)d_in[0];
    const float* Wq    = (const float*)d_in[1];
    const float* bq    = (const float*)d_in[2];
    const float* Wk    = (const float*)d_in[3];
    const float* bk    = (const float*)d_in[4];
    const float* Wv    = (const float*)d_in[5];
    const float* bv    = (const float*)d_in[6];
    const float* Wo    = (const float*)d_in[7];
    const float* bo    = (const float*)d_in[8];
    const float* Wp    = (const float*)d_in[9];
    const float* bp    = (const float*)d_in[10];
    const float* alpha = (const float*)d_in[11];
    float* out = (float*)d_out;

    __half *pQ, *pK, *pV;
    float *pO, *pc, *ps;
    cudaGetSymbolAddress((void**)&pQ, g_Qf);
    cudaGetSymbolAddress((void**)&pK, g_Kf);
    cudaGetSymbolAddress((void**)&pV, g_Vf);
    cudaGetSymbolAddress((void**)&pO, g_O);
    cudaGetSymbolAddress((void**)&pc, g_cs);
    cudaGetSymbolAddress((void**)&ps, g_sn);

    cudaFuncSetAttribute(gemm_mma<0>, cudaFuncAttributeMaxDynamicSharedMemorySize, MMA_SMEM_BYTES);
    cudaFuncSetAttribute(gemm_mma<1>, cudaFuncAttributeMaxDynamicSharedMemorySize, MMA_SMEM_BYTES);
    cudaFuncSetAttribute(phase_kernel3, cudaFuncAttributeMaxDynamicSharedMemorySize, PHASE_SMEM_BYTES);
    cudaFuncSetAttribute(attn_f16, cudaFuncAttributeMaxDynamicSharedMemorySize, ATT_SMEM_BYTES);

    dim3 g(DMODEL / 128, NTOK / 128);   // (8, 32)

    gemm_mma<1><<<g, 256, MMA_SMEM_BYTES>>>(x, Wq, bq, nullptr, pQ,
                                            0.125f * LOG2E, NTOK, DMODEL, DMODEL);
    gemm_mma<1><<<g, 256, MMA_SMEM_BYTES>>>(x, Wk, bk, nullptr, pK, 1.0f,
                                            NTOK, DMODEL, DMODEL);
    gemm_mma<1><<<g, 256, MMA_SMEM_BYTES>>>(x, Wv, bv, nullptr, pV, 1.0f,
                                            NTOK, DMODEL, DMODEL);
    phase_kernel3<<<NTOK / 16, 256, PHASE_SMEM_BYTES>>>(x, Wp, bp, pc, ps);

    attn_f16<<<dim3(S_LEN / 128, BHALL), 256, ATT_SMEM_BYTES>>>(pc, ps, alpha, pO);

    gemm_mma<0><<<g, 256, MMA_SMEM_BYTES>>>(pO, Wo, bo, out, nullptr, 1.0f,
                                            NTOK, DMODEL, DMODEL);
}

// round 15
// speedup vs baseline: 1.6633x; 1.1790x over previous
#include <cuda_runtime.h>
#include <cuda_bf16.h>
#include <cuda_fp16.h>
#include <math.h>
#include <stdint.h>

#define S_LEN   2048
#define DMODEL  1024
#define NHEADS  16
#define DK      64
#define BATCH   2
#define NTOK    (BATCH * S_LEN)
#define BHALL   (BATCH * NHEADS)
#define LOG2E   1.44269504f

__device__ __align__(256) __half g_Qf[BHALL * S_LEN * DK];
__device__ __align__(256) __half g_Kf[BHALL * S_LEN * DK];
__device__ __align__(256) __half g_Vf[BHALL * S_LEN * DK];
__device__ float g_O[NTOK * DMODEL];
__device__ float g_cs[BHALL * S_LEN];
__device__ float g_sn[BHALL * S_LEN];

// ============================ helpers ============================
__device__ __forceinline__ unsigned sptr(const void* p) {
    return (unsigned)__cvta_generic_to_shared(p);
}
__device__ __forceinline__ void ldsm_x4(unsigned r[4], unsigned sa) {
    asm volatile("ldmatrix.sync.aligned.m8n8.x4.shared.b16 {%0,%1,%2,%3}, [%4];"
                 : "=r"(r[0]), "=r"(r[1]), "=r"(r[2]), "=r"(r[3]) : "r"(sa));
}
__device__ __forceinline__ void ldsm_x4t(unsigned r[4], unsigned sa) {
    asm volatile("ldmatrix.sync.aligned.m8n8.x4.trans.shared.b16 {%0,%1,%2,%3}, [%4];"
                 : "=r"(r[0]), "=r"(r[1]), "=r"(r[2]), "=r"(r[3]) : "r"(sa));
}
__device__ __forceinline__ void mma_f16(float c[4], const unsigned a[4], const unsigned b[2]) {
    asm volatile(
        "mma.sync.aligned.m16n8k16.row.col.f32.f16.f16.f32 "
        "{%0,%1,%2,%3}, {%4,%5,%6,%7}, {%8,%9}, {%0,%1,%2,%3};"
        : "+f"(c[0]), "+f"(c[1]), "+f"(c[2]), "+f"(c[3])
        : "r"(a[0]), "r"(a[1]), "r"(a[2]), "r"(a[3]), "r"(b[0]), "r"(b[1]));
}
__device__ __forceinline__ void cpa16(unsigned d, const void* s) {
    asm volatile("cp.async.cg.shared.global [%0], [%1], 16;" :: "r"(d), "l"(s));
}
__device__ __forceinline__ void cp_commit() { asm volatile("cp.async.commit_group;"); }
template <int N> __device__ __forceinline__ void cp_wait() {
    asm volatile("cp.async.wait_group %0;" :: "n"(N));
}
__device__ __forceinline__ unsigned packh2(float e0, float e1) {
    const __half2 h = __floats2half2_rn(e0, e1);
    return *reinterpret_cast<const unsigned*>(&h);
}
// fp16 hi/lo split of a float pair
__device__ __forceinline__ void hilo2h(float e0, float e1, unsigned& hi, unsigned& lo) {
    const __half h0 = __float2half_rn(e0);
    const __half h1 = __float2half_rn(e1);
    __half2 hp; hp.x = h0; hp.y = h1;
    hi = *reinterpret_cast<const unsigned*>(&hp);
    lo = packh2(e0 - __half2float(h0), e1 - __half2float(h1));
}
__device__ __forceinline__ float ex2(float x) {
    float r;
    asm("ex2.approx.f32 %0, %1;" : "=f"(r) : "f"(x));
    return r;
}

// ============================================================================
// GEMM fp16 2-term: D = A @ B + bias.  A split hi/lo fp16 (rounding of A
// corrected); B single fp16.  mma per k16-slice: 2mt x 8nt x 2 = 32.
// MODE 0: fp32 C[m*N+n].  MODE 1: __half head-major Cf[(bh*S+s)*64+d] * scl.
// ============================================================================
#define ASTR 40
#define BSTR 136
#define A_ELEMS (128 * ASTR)              // 5120
#define B_ELEMS (32 * BSTR)               // 4352
#define BUF_ELEMS (2 * A_ELEMS + B_ELEMS) // 14592
#define MMA_SMEM_BYTES (2 * BUF_ELEMS * 2)  // 58368

template <int MODE>
__global__ void __launch_bounds__(256) gemm_h2(
    const float* __restrict__ A, const float* __restrict__ B,
    const float* __restrict__ bias, float* __restrict__ C,
    __half* __restrict__ Cf, float scl, int M, int N, int K)
{
    extern __shared__ __half smh[];
    const int tid  = threadIdx.x;
    const int lane = tid & 31;
    const int warp = tid >> 5;
    const int wm = (warp >> 1) * 32;
    const int wn = (warp & 1) * 64;
    const int m0 = blockIdx.y * 128;
    const int n0 = blockIdx.x * 128;

    int arow[4], acol[4], brow[4], bcol[4];
#pragma unroll
    for (int j = 0; j < 4; j++) {
        const int idx = tid + j * 256;
        arow[j] = idx >> 3;  acol[j] = (idx & 7) << 2;
        brow[j] = idx >> 5;  bcol[j] = (idx & 31) << 2;
    }

    float4 pa[4], pb[4];
#pragma unroll
    for (int j = 0; j < 4; j++) {
        pa[j] = *(const float4*)&A[(size_t)(m0 + arow[j]) * K + acol[j]];
        pb[j] = *(const float4*)&B[(size_t)brow[j] * N + n0 + bcol[j]];
    }
    {
        __half* Ah = smh;
        __half* Al = Ah + A_ELEMS;
        __half* Bh = smh + 2 * A_ELEMS;
#pragma unroll
        for (int j = 0; j < 4; j++) {
            unsigned h01, h23, l01, l23;
            hilo2h(pa[j].x, pa[j].y, h01, l01);
            hilo2h(pa[j].z, pa[j].w, h23, l23);
            *reinterpret_cast<uint2*>(&Ah[arow[j] * ASTR + acol[j]]) = make_uint2(h01, h23);
            *reinterpret_cast<uint2*>(&Al[arow[j] * ASTR + acol[j]]) = make_uint2(l01, l23);
            *reinterpret_cast<uint2*>(&Bh[brow[j] * BSTR + bcol[j]]) =
                make_uint2(packh2(pb[j].x, pb[j].y), packh2(pb[j].z, pb[j].w));
        }
    }
    __syncthreads();

    float acc[2][8][4];
#pragma unroll
    for (int mt = 0; mt < 2; mt++)
#pragma unroll
        for (int nt = 0; nt < 8; nt++)
#pragma unroll
            for (int e = 0; e < 4; e++) acc[mt][nt][e] = 0.f;

    const int KT = K / 32;
    for (int kt = 0; kt < KT; ++kt) {
        const int buf = kt & 1;
        if (kt + 1 < KT) {
            const int k0 = (kt + 1) * 32;
#pragma unroll
            for (int j = 0; j < 4; j++) {
                pa[j] = *(const float4*)&A[(size_t)(m0 + arow[j]) * K + k0 + acol[j]];
                pb[j] = *(const float4*)&B[(size_t)(k0 + brow[j]) * N + n0 + bcol[j]];
            }
        }

        const __half* Ah = smh + buf * BUF_ELEMS;
        const __half* Bh = smh + buf * BUF_ELEMS + 2 * A_ELEMS;

#pragma unroll
        for (int kk = 0; kk < 32; kk += 16) {
            unsigned afh[2][4], afl[2][4];
#pragma unroll
            for (int mt = 0; mt < 2; mt++) {
                unsigned sa = sptr(&Ah[(wm + mt * 16 + (lane & 15)) * ASTR
                                       + kk + ((lane >> 4) << 3)]);
                ldsm_x4(afh[mt], sa);
                ldsm_x4(afl[mt], sa + A_ELEMS * 2);
            }
            unsigned bfh[8][2];
#pragma unroll
            for (int np = 0; np < 4; np++) {
                unsigned sb = sptr(&Bh[(kk + (lane & 15)) * BSTR
                                       + wn + np * 16 + ((lane >> 4) << 3)]);
                unsigned r[4];
                ldsm_x4t(r, sb);
                bfh[2 * np][0] = r[0]; bfh[2 * np][1] = r[1];
                bfh[2 * np + 1][0] = r[2]; bfh[2 * np + 1][1] = r[3];
            }
#pragma unroll
            for (int mt = 0; mt < 2; mt++)
#pragma unroll
                for (int nt = 0; nt < 8; nt++) {
                    mma_f16(acc[mt][nt], afh[mt], bfh[nt]);
                    mma_f16(acc[mt][nt], afl[mt], bfh[nt]);
                }
        }

        if (kt + 1 < KT) {
            const int nb = 1 - buf;
            __half* nAh = smh + nb * BUF_ELEMS;
            __half* nAl = nAh + A_ELEMS;
            __half* nBh = smh + nb * BUF_ELEMS + 2 * A_ELEMS;
#pragma unroll
            for (int j = 0; j < 4; j++) {
                unsigned h01, h23, l01, l23;
                hilo2h(pa[j].x, pa[j].y, h01, l01);
                hilo2h(pa[j].z, pa[j].w, h23, l23);
                *reinterpret_cast<uint2*>(&nAh[arow[j] * ASTR + acol[j]]) = make_uint2(h01, h23);
                *reinterpret_cast<uint2*>(&nAl[arow[j] * ASTR + acol[j]]) = make_uint2(l01, l23);
                *reinterpret_cast<uint2*>(&nBh[brow[j] * BSTR + bcol[j]]) =
                    make_uint2(packh2(pb[j].x, pb[j].y), packh2(pb[j].z, pb[j].w));
            }
            __syncthreads();
        }
    }

#pragma unroll
    for (int mt = 0; mt < 2; mt++) {
        const int r0 = m0 + wm + mt * 16 + (lane >> 2);
#pragma unroll
        for (int nt = 0; nt < 8; nt++) {
            const int c = n0 + wn + nt * 8 + ((lane & 3) << 1);
            const float b0v = bias[c], b1v = bias[c + 1];
            const float v00 = acc[mt][nt][0] + b0v;
            const float v01 = acc[mt][nt][1] + b1v;
            const float v10 = acc[mt][nt][2] + b0v;
            const float v11 = acc[mt][nt][3] + b1v;
            if (MODE == 0) {
                *(float2*)&C[(size_t)r0 * N + c]       = make_float2(v00, v01);
                *(float2*)&C[(size_t)(r0 + 8) * N + c] = make_float2(v10, v11);
            } else {
                const int s = r0 & 2047;
                const int h = c >> 6, d = c & 63;
                const int bh = (r0 >> 11) * NHEADS + h;
                const size_t i0 = ((size_t)bh * S_LEN + s) * DK + d;
                const size_t i1 = ((size_t)bh * S_LEN + s + 8) * DK + d;
                *(unsigned*)&Cf[i0] = packh2(v00 * scl, v01 * scl);
                *(unsigned*)&Cf[i1] = packh2(v10 * scl, v11 * scl);
            }
        }
    }
}

// ============================ phase kernel ============================
#define WPT_STRIDE 1032
#define PHASE_SMEM_BYTES (16 * WPT_STRIDE * 4)

__global__ void __launch_bounds__(256) phase_kernel3(
    const float* __restrict__ x, const float* __restrict__ Wp,
    const float* __restrict__ bp, float* __restrict__ cs, float* __restrict__ sn)
{
    extern __shared__ float WpT[];
    const int tid = threadIdx.x;
    for (int idx = tid; idx < DMODEL * NHEADS; idx += 256) {
        const int k = idx >> 4, h = idx & 15;
        WpT[h * WPT_STRIDE + k] = Wp[idx];
    }
    __syncthreads();

    const int lane = tid & 31;
    const int warp = tid >> 5;
    const int t0 = blockIdx.x * 16 + warp * 2;

    float a0[NHEADS], a1[NHEADS];
#pragma unroll
    for (int h = 0; h < NHEADS; h++) { a0[h] = 0.f; a1[h] = 0.f; }
#pragma unroll 4
    for (int i = 0; i < 32; ++i) {
        const int k = i * 32 + lane;
        const float x0 = x[(size_t)t0 * DMODEL + k];
        const float x1 = x[(size_t)(t0 + 1) * DMODEL + k];
#pragma unroll
        for (int h = 0; h < NHEADS; h++) {
            const float w = WpT[h * WPT_STRIDE + k];
            a0[h] = fmaf(x0, w, a0[h]);
            a1[h] = fmaf(x1, w, a1[h]);
        }
    }
    float p0 = 0.f, p1 = 0.f;
#pragma unroll
    for (int h = 0; h < NHEADS; h++) {
        float v0 = a0[h], v1 = a1[h];
#pragma unroll
        for (int off = 16; off >= 1; off >>= 1) {
            v0 += __shfl_xor_sync(0xffffffffu, v0, off);
            v1 += __shfl_xor_sync(0xffffffffu, v1, off);
        }
        if (lane == h) { p0 = v0; p1 = v1; }
    }
    if (lane < NHEADS) {
        const float bpl = bp[lane];
#pragma unroll
        for (int u = 0; u < 2; u++) {
            const int t = t0 + u;
            const int bh = (t >> 11) * NHEADS + lane;
            float sv, cv;
            sincosf((u ? p1 : p0) + bpl, &sv, &cv);
            cs[bh * S_LEN + (t & 2047)] = cv;
            sn[bh * S_LEN + (t & 2047)] = sv;
        }
    }
}

// ============================================================================
// Attention (R14-proven): single fp16 mma, TQ=128 x TK=64, 2 CTAs/SM, exp2.
// ============================================================================
#define TSTR   72
#define QF_E   (128 * TSTR)
#define KVT_E  (64 * TSTR)
#define BUF0_E QF_E
#define BUFBLK_E (2 * KVT_E)
#define KC_BYTE_OFF ((QF_E + 2 * BUFBLK_E) * 2)
#define ATT_SMEM_BYTES (KC_BYTE_OFF + 2 * 128 * 4)

__global__ void __launch_bounds__(256, 2) attn_f16(
    const float* __restrict__ cs, const float* __restrict__ sn,
    const float* __restrict__ alpha, float* __restrict__ O)
{
    extern __shared__ __half smh[];
    const unsigned sbase = sptr(smh);
    const int tid  = threadIdx.x;
    const int lane = tid & 31;
    const int warp = tid >> 5;
    const int bh = blockIdx.y;
    const int q0 = blockIdx.x * 128;

#pragma unroll
    for (int j = 0; j < 4; j++) {
        const int idx = tid + j * 256;
        const int row = idx >> 3, ch = idx & 7;
        cpa16(sbase + (row * TSTR + ch * 8) * 2,
              g_Qf + ((size_t)(bh * S_LEN + q0 + row) * DK + ch * 8));
    }
#pragma unroll 1
    for (int pre = 0; pre < 2; pre++) {
        const int c0 = pre * 64;
        const unsigned kb = sbase + (BUF0_E + pre * BUFBLK_E) * 2;
#pragma unroll
        for (int j = 0; j < 2; j++) {
            const int idx = tid + j * 256;
            const int row = idx >> 3, ch = idx & 7;
            const unsigned off = (row * TSTR + ch * 8) * 2;
            cpa16(kb + off,             g_Kf + ((size_t)(bh * S_LEN + c0 + row) * DK + ch * 8));
            cpa16(kb + KVT_E * 2 + off, g_Vf + ((size_t)(bh * S_LEN + c0 + row) * DK + ch * 8));
        }
        if (tid < 32) {
            const int arr = tid >> 4, q = tid & 15;
            const float* s = arr ? sn : cs;
            cpa16(sbase + KC_BYTE_OFF + pre * 512 + arr * 256 + q * 16,
                  s + (size_t)bh * S_LEN + c0 + q * 4);
        }
        cp_commit();
    }

    const float alp = alpha[bh & (NHEADS - 1)] * LOG2E;
    const int rq_lo = q0 + warp * 16 + (lane >> 2);
    const float aqc_lo = alp * cs[bh * S_LEN + rq_lo];
    const float aqs_lo = alp * sn[bh * S_LEN + rq_lo];
    const float aqc_hi = alp * cs[bh * S_LEN + rq_lo + 8];
    const float aqs_hi = alp * sn[bh * S_LEN + rq_lo + 8];

    cp_wait<1>();
    __syncthreads();

    const int koff = (lane >> 4) << 3;
    const unsigned qrow = (warp * 16 + (lane & 15)) * TSTR;
    unsigned afq[4][4];
#pragma unroll
    for (int ks = 0; ks < 4; ks++)
        ldsm_x4(afq[ks], sbase + (qrow + ks * 16 + koff) * 2);

    float m_lo = -1e30f, m_hi = -1e30f, l_lo = 0.f, l_hi = 0.f;
    float o[8][4];
#pragma unroll
    for (int nt = 0; nt < 8; nt++)
#pragma unroll
        for (int e = 0; e < 4; e++) o[nt][e] = 0.f;

    const float* fkc = (const float*)((const char*)smh + KC_BYTE_OFF);

    for (int kt = 0; kt < S_LEN / 64; ++kt) {
        if (kt) { cp_wait<1>(); __syncthreads(); }
        const int buf = kt & 1;
        const unsigned kb = sbase + (BUF0_E + buf * BUFBLK_E) * 2;

        float acc[8][4];
#pragma unroll
        for (int t = 0; t < 8; t++)
#pragma unroll
            for (int e = 0; e < 4; e++) acc[t][e] = 0.f;

#pragma unroll
        for (int ks = 0; ks < 4; ks++) {
#pragma unroll
            for (int p = 0; p < 4; p++) {
                unsigned rh[4];
                ldsm_x4(rh, kb + ((p * 16 + (lane & 15)) * TSTR + ks * 16 + koff) * 2);
                unsigned b0[2] = {rh[0], rh[2]}, b1[2] = {rh[1], rh[3]};
                mma_f16(acc[2 * p],     afq[ks], b0);
                mma_f16(acc[2 * p + 1], afq[ks], b1);
            }
        }

        const float* kcb = fkc + buf * 128;
        float mx_lo = -1e30f, mx_hi = -1e30f;
#pragma unroll
        for (int t = 0; t < 8; t++) {
            const float2 kc2 = *(const float2*)&kcb[t * 8 + ((lane & 3) << 1)];
            const float2 ks2 = *(const float2*)&kcb[64 + t * 8 + ((lane & 3) << 1)];
            acc[t][0] += aqc_lo * kc2.x + aqs_lo * ks2.x;
            acc[t][1] += aqc_lo * kc2.y + aqs_lo * ks2.y;
            acc[t][2] += aqc_hi * kc2.x + aqs_hi * ks2.x;
            acc[t][3] += aqc_hi * kc2.y + aqs_hi * ks2.y;
            mx_lo = fmaxf(mx_lo, fmaxf(acc[t][0], acc[t][1]));
            mx_hi = fmaxf(mx_hi, fmaxf(acc[t][2], acc[t][3]));
        }
        mx_lo = fmaxf(mx_lo, __shfl_xor_sync(0xffffffffu, mx_lo, 1));
        mx_lo = fmaxf(mx_lo, __shfl_xor_sync(0xffffffffu, mx_lo, 2));
        mx_hi = fmaxf(mx_hi, __shfl_xor_sync(0xffffffffu, mx_hi, 1));
        mx_hi = fmaxf(mx_hi, __shfl_xor_sync(0xffffffffu, mx_hi, 2));

        const float mn_lo = fmaxf(m_lo, mx_lo);
        const float mn_hi = fmaxf(m_hi, mx_hi);
        const float cr_lo = ex2(m_lo - mn_lo);
        const float cr_hi = ex2(m_hi - mn_hi);
        m_lo = mn_lo; m_hi = mn_hi;

        float sum_lo = 0.f, sum_hi = 0.f;
#pragma unroll
        for (int t = 0; t < 8; t++) {
            acc[t][0] = ex2(acc[t][0] - m_lo); sum_lo += acc[t][0];
            acc[t][1] = ex2(acc[t][1] - m_lo); sum_lo += acc[t][1];
            acc[t][2] = ex2(acc[t][2] - m_hi); sum_hi += acc[t][2];
            acc[t][3] = ex2(acc[t][3] - m_hi); sum_hi += acc[t][3];
        }
        sum_lo += __shfl_xor_sync(0xffffffffu, sum_lo, 1);
        sum_lo += __shfl_xor_sync(0xffffffffu, sum_lo, 2);
        sum_hi += __shfl_xor_sync(0xffffffffu, sum_hi, 1);
        sum_hi += __shfl_xor_sync(0xffffffffu, sum_hi, 2);
        l_lo = l_lo * cr_lo + sum_lo;
        l_hi = l_hi * cr_hi + sum_hi;

#pragma unroll
        for (int nt = 0; nt < 8; nt++) {
            o[nt][0] *= cr_lo; o[nt][1] *= cr_lo;
            o[nt][2] *= cr_hi; o[nt][3] *= cr_hi;
        }

        const unsigned vb = kb + KVT_E * 2;
#pragma unroll
        for (int t2 = 0; t2 < 4; t2++) {
            unsigned aP[4];
            aP[0] = packh2(acc[2 * t2][0],     acc[2 * t2][1]);
            aP[1] = packh2(acc[2 * t2][2],     acc[2 * t2][3]);
            aP[2] = packh2(acc[2 * t2 + 1][0], acc[2 * t2 + 1][1]);
            aP[3] = packh2(acc[2 * t2 + 1][2], acc[2 * t2 + 1][3]);
#pragma unroll
            for (int dp = 0; dp < 4; dp++) {
                unsigned rh[4];
                ldsm_x4t(rh, vb + ((t2 * 16 + (lane & 15)) * TSTR + dp * 16 + koff) * 2);
                unsigned b0[2] = {rh[0], rh[1]}, b1[2] = {rh[2], rh[3]};
                mma_f16(o[2 * dp],     aP, b0);
                mma_f16(o[2 * dp + 1], aP, b1);
            }
        }

        __syncthreads();
        if (kt + 2 < S_LEN / 64) {
            const int c0 = (kt + 2) * 64;
            const unsigned nb = sbase + (BUF0_E + buf * BUFBLK_E) * 2;
#pragma unroll
            for (int j = 0; j < 2; j++) {
                const int idx = tid + j * 256;
                const int row = idx >> 3, ch = idx & 7;
                const unsigned off = (row * TSTR + ch * 8) * 2;
                cpa16(nb + off,             g_Kf + ((size_t)(bh * S_LEN + c0 + row) * DK + ch * 8));
                cpa16(nb + KVT_E * 2 + off, g_Vf + ((size_t)(bh * S_LEN + c0 + row) * DK + ch * 8));
            }
            if (tid < 32) {
                const int arr = tid >> 4, q = tid & 15;
                const float* s = arr ? sn : cs;
                cpa16(sbase + KC_BYTE_OFF + buf * 512 + arr * 256 + q * 16,
                      s + (size_t)bh * S_LEN + c0 + q * 4);
            }
        }
        cp_commit();
    }

    const int b = bh >> 4, h = bh & 15;
    const float inv_lo = 1.f / l_lo;
    const float inv_hi = 1.f / l_hi;
    const int row_lo = q0 + warp * 16 + (lane >> 2);
#pragma unroll
    for (int nt = 0; nt < 8; nt++) {
        const int col = h * DK + nt * 8 + ((lane & 3) << 1);
        *(float2*)&O[((size_t)b * S_LEN + row_lo) * DMODEL + col] =
            make_float2(o[nt][0] * inv_lo, o[nt][1] * inv_lo);
        *(float2*)&O[((size_t)b * S_LEN + row_lo + 8) * DMODEL + col] =
            make_float2(o[nt][2] * inv_hi, o[nt][3] * inv_hi);
    }
}

// ============================================================================
extern "C" void kernel_launch(void* const* d_in, const int* in_sizes, int n_in,
                              void* d_out, int out_size)
{
    const float* x     = (const float*)d_in[0];
    const float* Wq    = (const float*)d_in[1];
    const float* bq    = (const float*)d_in[2];
    const float* Wk    = (const float*)d_in[3];
    const float* bk    = (const float*)d_in[4];
    const float* Wv    = (const float*)d_in[5];
    const float* bv    = (const float*)d_in[6];
    const float* Wo    = (const float*)d_in[7];
    const float* bo    = (const float*)d_in[8];
    const float* Wp    = (const float*)d_in[9];
    const float* bp    = (const float*)d_in[10];
    const float* alpha = (const float*)d_in[11];
    float* out = (float*)d_out;

    __half *pQ, *pK, *pV;
    float *pO, *pc, *ps;
    cudaGetSymbolAddress((void**)&pQ, g_Qf);
    cudaGetSymbolAddress((void**)&pK, g_Kf);
    cudaGetSymbolAddress((void**)&pV, g_Vf);
    cudaGetSymbolAddress((void**)&pO, g_O);
    cudaGetSymbolAddress((void**)&pc, g_cs);
    cudaGetSymbolAddress((void**)&ps, g_sn);

    cudaFuncSetAttribute(gemm_h2<0>, cudaFuncAttributeMaxDynamicSharedMemorySize, MMA_SMEM_BYTES);
    cudaFuncSetAttribute(gemm_h2<1>, cudaFuncAttributeMaxDynamicSharedMemorySize, MMA_SMEM_BYTES);
    cudaFuncSetAttribute(phase_kernel3, cudaFuncAttributeMaxDynamicSharedMemorySize, PHASE_SMEM_BYTES);
    cudaFuncSetAttribute(attn_f16, cudaFuncAttributeMaxDynamicSharedMemorySize, ATT_SMEM_BYTES);

    dim3 g(DMODEL / 128, NTOK / 128);   // (8, 32)

    gemm_h2<1><<<g, 256, MMA_SMEM_BYTES>>>(x, Wq, bq, nullptr, pQ,
                                           0.125f * LOG2E, NTOK, DMODEL, DMODEL);
    gemm_h2<1><<<g, 256, MMA_SMEM_BYTES>>>(x, Wk, bk, nullptr, pK, 1.0f,
                                           NTOK, DMODEL, DMODEL);
    gemm_h2<1><<<g, 256, MMA_SMEM_BYTES>>>(x, Wv, bv, nullptr, pV, 1.0f,
                                           NTOK, DMODEL, DMODEL);
    phase_kernel3<<<NTOK / 16, 256, PHASE_SMEM_BYTES>>>(x, Wp, bp, pc, ps);

    attn_f16<<<dim3(S_LEN / 128, BHALL), 256, ATT_SMEM_BYTES>>>(pc, ps, alpha, pO);

    gemm_h2<0><<<g, 256, MMA_SMEM_BYTES>>>(pO, Wo, bo, out, nullptr, 1.0f,
                                           NTOK, DMODEL, DMODEL);
}

// round 16
// speedup vs baseline: 1.9310x; 1.1610x over previous
#include <cuda_runtime.h>
#include <cuda_bf16.h>
#include <cuda_fp16.h>
#include <math.h>
#include <stdint.h>

#define S_LEN   2048
#define DMODEL  1024
#define NHEADS  16
#define DK      64
#define BATCH   2
#define NTOK    (BATCH * S_LEN)
#define BHALL   (BATCH * NHEADS)
#define LOG2E   1.44269504f

__device__ __align__(256) __half g_Qf[BHALL * S_LEN * DK];
__device__ __align__(256) __half g_Kf[BHALL * S_LEN * DK];
__device__ __align__(256) __half g_Vf[BHALL * S_LEN * DK];
__device__ float g_O[NTOK * DMODEL];
__device__ float g_cs[BHALL * S_LEN];
__device__ float g_sn[BHALL * S_LEN];

// ============================ helpers ============================
__device__ __forceinline__ unsigned sptr(const void* p) {
    return (unsigned)__cvta_generic_to_shared(p);
}
__device__ __forceinline__ void ldsm_x4(unsigned r[4], unsigned sa) {
    asm volatile("ldmatrix.sync.aligned.m8n8.x4.shared.b16 {%0,%1,%2,%3}, [%4];"
                 : "=r"(r[0]), "=r"(r[1]), "=r"(r[2]), "=r"(r[3]) : "r"(sa));
}
__device__ __forceinline__ void ldsm_x4t(unsigned r[4], unsigned sa) {
    asm volatile("ldmatrix.sync.aligned.m8n8.x4.trans.shared.b16 {%0,%1,%2,%3}, [%4];"
                 : "=r"(r[0]), "=r"(r[1]), "=r"(r[2]), "=r"(r[3]) : "r"(sa));
}
__device__ __forceinline__ void mma_f16(float c[4], const unsigned a[4], const unsigned b[2]) {
    asm volatile(
        "mma.sync.aligned.m16n8k16.row.col.f32.f16.f16.f32 "
        "{%0,%1,%2,%3}, {%4,%5,%6,%7}, {%8,%9}, {%0,%1,%2,%3};"
        : "+f"(c[0]), "+f"(c[1]), "+f"(c[2]), "+f"(c[3])
        : "r"(a[0]), "r"(a[1]), "r"(a[2]), "r"(a[3]), "r"(b[0]), "r"(b[1]));
}
__device__ __forceinline__ void cpa16(unsigned d, const void* s) {
    asm volatile("cp.async.cg.shared.global [%0], [%1], 16;" :: "r"(d), "l"(s));
}
__device__ __forceinline__ void cp_commit() { asm volatile("cp.async.commit_group;"); }
template <int N> __device__ __forceinline__ void cp_wait() {
    asm volatile("cp.async.wait_group %0;" :: "n"(N));
}
__device__ __forceinline__ unsigned packh2(float e0, float e1) {
    const __half2 h = __floats2half2_rn(e0, e1);
    return *reinterpret_cast<const unsigned*>(&h);
}
__device__ __forceinline__ float ex2(float x) {
    float r;
    asm("ex2.approx.f32 %0, %1;" : "=f"(r) : "f"(x));
    return r;
}

// ============================================================================
// GEMM single fp16: D = A @ B + bias.  16 mma per k16-slice.
// MODE 0: fp32 C[m*N+n].  MODE 1: __half head-major Cf[(bh*S+s)*64+d] * scl.
// ============================================================================
#define ASTR 40
#define BSTR 136
#define A_ELEMS (128 * ASTR)              // 5120
#define B_ELEMS (32 * BSTR)               // 4352
#define BUF_ELEMS (A_ELEMS + B_ELEMS)     // 9472
#define MMA_SMEM_BYTES (2 * BUF_ELEMS * 2)  // 37888

template <int MODE>
__global__ void __launch_bounds__(256) gemm_h1(
    const float* __restrict__ A, const float* __restrict__ B,
    const float* __restrict__ bias, float* __restrict__ C,
    __half* __restrict__ Cf, float scl, int M, int N, int K)
{
    extern __shared__ __half smh[];
    const int tid  = threadIdx.x;
    const int lane = tid & 31;
    const int warp = tid >> 5;
    const int wm = (warp >> 1) * 32;
    const int wn = (warp & 1) * 64;
    const int m0 = blockIdx.y * 128;
    const int n0 = blockIdx.x * 128;

    int arow[4], acol[4], brow[4], bcol[4];
#pragma unroll
    for (int j = 0; j < 4; j++) {
        const int idx = tid + j * 256;
        arow[j] = idx >> 3;  acol[j] = (idx & 7) << 2;
        brow[j] = idx >> 5;  bcol[j] = (idx & 31) << 2;
    }

    float4 pa[4], pb[4];
#pragma unroll
    for (int j = 0; j < 4; j++) {
        pa[j] = *(const float4*)&A[(size_t)(m0 + arow[j]) * K + acol[j]];
        pb[j] = *(const float4*)&B[(size_t)brow[j] * N + n0 + bcol[j]];
    }
    {
        __half* Ah = smh;
        __half* Bh = smh + A_ELEMS;
#pragma unroll
        for (int j = 0; j < 4; j++) {
            *reinterpret_cast<uint2*>(&Ah[arow[j] * ASTR + acol[j]]) =
                make_uint2(packh2(pa[j].x, pa[j].y), packh2(pa[j].z, pa[j].w));
            *reinterpret_cast<uint2*>(&Bh[brow[j] * BSTR + bcol[j]]) =
                make_uint2(packh2(pb[j].x, pb[j].y), packh2(pb[j].z, pb[j].w));
        }
    }
    __syncthreads();

    float acc[2][8][4];
#pragma unroll
    for (int mt = 0; mt < 2; mt++)
#pragma unroll
        for (int nt = 0; nt < 8; nt++)
#pragma unroll
            for (int e = 0; e < 4; e++) acc[mt][nt][e] = 0.f;

    const int KT = K / 32;
    for (int kt = 0; kt < KT; ++kt) {
        const int buf = kt & 1;
        if (kt + 1 < KT) {
            const int k0 = (kt + 1) * 32;
#pragma unroll
            for (int j = 0; j < 4; j++) {
                pa[j] = *(const float4*)&A[(size_t)(m0 + arow[j]) * K + k0 + acol[j]];
                pb[j] = *(const float4*)&B[(size_t)(k0 + brow[j]) * N + n0 + bcol[j]];
            }
        }

        const __half* Ah = smh + buf * BUF_ELEMS;
        const __half* Bh = smh + buf * BUF_ELEMS + A_ELEMS;

#pragma unroll
        for (int kk = 0; kk < 32; kk += 16) {
            unsigned af[2][4];
#pragma unroll
            for (int mt = 0; mt < 2; mt++) {
                unsigned sa = sptr(&Ah[(wm + mt * 16 + (lane & 15)) * ASTR
                                       + kk + ((lane >> 4) << 3)]);
                ldsm_x4(af[mt], sa);
            }
            unsigned bf[8][2];
#pragma unroll
            for (int np = 0; np < 4; np++) {
                unsigned sb = sptr(&Bh[(kk + (lane & 15)) * BSTR
                                       + wn + np * 16 + ((lane >> 4) << 3)]);
                unsigned r[4];
                ldsm_x4t(r, sb);
                bf[2 * np][0] = r[0]; bf[2 * np][1] = r[1];
                bf[2 * np + 1][0] = r[2]; bf[2 * np + 1][1] = r[3];
            }
#pragma unroll
            for (int mt = 0; mt < 2; mt++)
#pragma unroll
                for (int nt = 0; nt < 8; nt++)
                    mma_f16(acc[mt][nt], af[mt], bf[nt]);
        }

        if (kt + 1 < KT) {
            const int nb = 1 - buf;
            __half* nAh = smh + nb * BUF_ELEMS;
            __half* nBh = smh + nb * BUF_ELEMS + A_ELEMS;
#pragma unroll
            for (int j = 0; j < 4; j++) {
                *reinterpret_cast<uint2*>(&nAh[arow[j] * ASTR + acol[j]]) =
                    make_uint2(packh2(pa[j].x, pa[j].y), packh2(pa[j].z, pa[j].w));
                *reinterpret_cast<uint2*>(&nBh[brow[j] * BSTR + bcol[j]]) =
                    make_uint2(packh2(pb[j].x, pb[j].y), packh2(pb[j].z, pb[j].w));
            }
            __syncthreads();
        }
    }

#pragma unroll
    for (int mt = 0; mt < 2; mt++) {
        const int r0 = m0 + wm + mt * 16 + (lane >> 2);
#pragma unroll
        for (int nt = 0; nt < 8; nt++) {
            const int c = n0 + wn + nt * 8 + ((lane & 3) << 1);
            const float b0v = bias[c], b1v = bias[c + 1];
            const float v00 = acc[mt][nt][0] + b0v;
            const float v01 = acc[mt][nt][1] + b1v;
            const float v10 = acc[mt][nt][2] + b0v;
            const float v11 = acc[mt][nt][3] + b1v;
            if (MODE == 0) {
                *(float2*)&C[(size_t)r0 * N + c]       = make_float2(v00, v01);
                *(float2*)&C[(size_t)(r0 + 8) * N + c] = make_float2(v10, v11);
            } else {
                const int s = r0 & 2047;
                const int h = c >> 6, d = c & 63;
                const int bh = (r0 >> 11) * NHEADS + h;
                const size_t i0 = ((size_t)bh * S_LEN + s) * DK + d;
                const size_t i1 = ((size_t)bh * S_LEN + s + 8) * DK + d;
                *(unsigned*)&Cf[i0] = packh2(v00 * scl, v01 * scl);
                *(unsigned*)&Cf[i1] = packh2(v10 * scl, v11 * scl);
            }
        }
    }
}

// ============================ phase kernel ============================
#define WPT_STRIDE 1032
#define PHASE_SMEM_BYTES (16 * WPT_STRIDE * 4)

__global__ void __launch_bounds__(256) phase_kernel3(
    const float* __restrict__ x, const float* __restrict__ Wp,
    const float* __restrict__ bp, float* __restrict__ cs, float* __restrict__ sn)
{
    extern __shared__ float WpT[];
    const int tid = threadIdx.x;
    for (int idx = tid; idx < DMODEL * NHEADS; idx += 256) {
        const int k = idx >> 4, h = idx & 15;
        WpT[h * WPT_STRIDE + k] = Wp[idx];
    }
    __syncthreads();

    const int lane = tid & 31;
    const int warp = tid >> 5;
    const int t0 = blockIdx.x * 16 + warp * 2;

    float a0[NHEADS], a1[NHEADS];
#pragma unroll
    for (int h = 0; h < NHEADS; h++) { a0[h] = 0.f; a1[h] = 0.f; }
#pragma unroll 4
    for (int i = 0; i < 32; ++i) {
        const int k = i * 32 + lane;
        const float x0 = x[(size_t)t0 * DMODEL + k];
        const float x1 = x[(size_t)(t0 + 1) * DMODEL + k];
#pragma unroll
        for (int h = 0; h < NHEADS; h++) {
            const float w = WpT[h * WPT_STRIDE + k];
            a0[h] = fmaf(x0, w, a0[h]);
            a1[h] = fmaf(x1, w, a1[h]);
        }
    }
    float p0 = 0.f, p1 = 0.f;
#pragma unroll
    for (int h = 0; h < NHEADS; h++) {
        float v0 = a0[h], v1 = a1[h];
#pragma unroll
        for (int off = 16; off >= 1; off >>= 1) {
            v0 += __shfl_xor_sync(0xffffffffu, v0, off);
            v1 += __shfl_xor_sync(0xffffffffu, v1, off);
        }
        if (lane == h) { p0 = v0; p1 = v1; }
    }
    if (lane < NHEADS) {
        const float bpl = bp[lane];
#pragma unroll
        for (int u = 0; u < 2; u++) {
            const int t = t0 + u;
            const int bh = (t >> 11) * NHEADS + lane;
            float sv, cv;
            sincosf((u ? p1 : p0) + bpl, &sv, &cv);
            cs[bh * S_LEN + (t & 2047)] = cv;
            sn[bh * S_LEN + (t & 2047)] = sv;
        }
    }
}

// ============================================================================
// Attention (R14/R15-proven): single fp16 mma, TQ=128 x TK=64, 2 CTAs/SM.
// ============================================================================
#define TSTR   72
#define QF_E   (128 * TSTR)
#define KVT_E  (64 * TSTR)
#define BUF0_E QF_E
#define BUFBLK_E (2 * KVT_E)
#define KC_BYTE_OFF ((QF_E + 2 * BUFBLK_E) * 2)
#define ATT_SMEM_BYTES (KC_BYTE_OFF + 2 * 128 * 4)

__global__ void __launch_bounds__(256, 2) attn_f16(
    const float* __restrict__ cs, const float* __restrict__ sn,
    const float* __restrict__ alpha, float* __restrict__ O)
{
    extern __shared__ __half smh[];
    const unsigned sbase = sptr(smh);
    const int tid  = threadIdx.x;
    const int lane = tid & 31;
    const int warp = tid >> 5;
    const int bh = blockIdx.y;
    const int q0 = blockIdx.x * 128;

#pragma unroll
    for (int j = 0; j < 4; j++) {
        const int idx = tid + j * 256;
        const int row = idx >> 3, ch = idx & 7;
        cpa16(sbase + (row * TSTR + ch * 8) * 2,
              g_Qf + ((size_t)(bh * S_LEN + q0 + row) * DK + ch * 8));
    }
#pragma unroll 1
    for (int pre = 0; pre < 2; pre++) {
        const int c0 = pre * 64;
        const unsigned kb = sbase + (BUF0_E + pre * BUFBLK_E) * 2;
#pragma unroll
        for (int j = 0; j < 2; j++) {
            const int idx = tid + j * 256;
            const int row = idx >> 3, ch = idx & 7;
            const unsigned off = (row * TSTR + ch * 8) * 2;
            cpa16(kb + off,             g_Kf + ((size_t)(bh * S_LEN + c0 + row) * DK + ch * 8));
            cpa16(kb + KVT_E * 2 + off, g_Vf + ((size_t)(bh * S_LEN + c0 + row) * DK + ch * 8));
        }
        if (tid < 32) {
            const int arr = tid >> 4, q = tid & 15;
            const float* s = arr ? sn : cs;
            cpa16(sbase + KC_BYTE_OFF + pre * 512 + arr * 256 + q * 16,
                  s + (size_t)bh * S_LEN + c0 + q * 4);
        }
        cp_commit();
    }

    const float alp = alpha[bh & (NHEADS - 1)] * LOG2E;
    const int rq_lo = q0 + warp * 16 + (lane >> 2);
    const float aqc_lo = alp * cs[bh * S_LEN + rq_lo];
    const float aqs_lo = alp * sn[bh * S_LEN + rq_lo];
    const float aqc_hi = alp * cs[bh * S_LEN + rq_lo + 8];
    const float aqs_hi = alp * sn[bh * S_LEN + rq_lo + 8];

    cp_wait<1>();
    __syncthreads();

    const int koff = (lane >> 4) << 3;
    const unsigned qrow = (warp * 16 + (lane & 15)) * TSTR;
    unsigned afq[4][4];
#pragma unroll
    for (int ks = 0; ks < 4; ks++)
        ldsm_x4(afq[ks], sbase + (qrow + ks * 16 + koff) * 2);

    float m_lo = -1e30f, m_hi = -1e30f, l_lo = 0.f, l_hi = 0.f;
    float o[8][4];
#pragma unroll
    for (int nt = 0; nt < 8; nt++)
#pragma unroll
        for (int e = 0; e < 4; e++) o[nt][e] = 0.f;

    const float* fkc = (const float*)((const char*)smh + KC_BYTE_OFF);

    for (int kt = 0; kt < S_LEN / 64; ++kt) {
        if (kt) { cp_wait<1>(); __syncthreads(); }
        const int buf = kt & 1;
        const unsigned kb = sbase + (BUF0_E + buf * BUFBLK_E) * 2;

        float acc[8][4];
#pragma unroll
        for (int t = 0; t < 8; t++)
#pragma unroll
            for (int e = 0; e < 4; e++) acc[t][e] = 0.f;

#pragma unroll
        for (int ks = 0; ks < 4; ks++) {
#pragma unroll
            for (int p = 0; p < 4; p++) {
                unsigned rh[4];
                ldsm_x4(rh, kb + ((p * 16 + (lane & 15)) * TSTR + ks * 16 + koff) * 2);
                unsigned b0[2] = {rh[0], rh[2]}, b1[2] = {rh[1], rh[3]};
                mma_f16(acc[2 * p],     afq[ks], b0);
                mma_f16(acc[2 * p + 1], afq[ks], b1);
            }
        }

        const float* kcb = fkc + buf * 128;
        float mx_lo = -1e30f, mx_hi = -1e30f;
#pragma unroll
        for (int t = 0; t < 8; t++) {
            const float2 kc2 = *(const float2*)&kcb[t * 8 + ((lane & 3) << 1)];
            const float2 ks2 = *(const float2*)&kcb[64 + t * 8 + ((lane & 3) << 1)];
            acc[t][0] += aqc_lo * kc2.x + aqs_lo * ks2.x;
            acc[t][1] += aqc_lo * kc2.y + aqs_lo * ks2.y;
            acc[t][2] += aqc_hi * kc2.x + aqs_hi * ks2.x;
            acc[t][3] += aqc_hi * kc2.y + aqs_hi * ks2.y;
            mx_lo = fmaxf(mx_lo, fmaxf(acc[t][0], acc[t][1]));
            mx_hi = fmaxf(mx_hi, fmaxf(acc[t][2], acc[t][3]));
        }
        mx_lo = fmaxf(mx_lo, __shfl_xor_sync(0xffffffffu, mx_lo, 1));
        mx_lo = fmaxf(mx_lo, __shfl_xor_sync(0xffffffffu, mx_lo, 2));
        mx_hi = fmaxf(mx_hi, __shfl_xor_sync(0xffffffffu, mx_hi, 1));
        mx_hi = fmaxf(mx_hi, __shfl_xor_sync(0xffffffffu, mx_hi, 2));

        const float mn_lo = fmaxf(m_lo, mx_lo);
        const float mn_hi = fmaxf(m_hi, mx_hi);
        const float cr_lo = ex2(m_lo - mn_lo);
        const float cr_hi = ex2(m_hi - mn_hi);
        m_lo = mn_lo; m_hi = mn_hi;

        float sum_lo = 0.f, sum_hi = 0.f;
#pragma unroll
        for (int t = 0; t < 8; t++) {
            acc[t][0] = ex2(acc[t][0] - m_lo); sum_lo += acc[t][0];
            acc[t][1] = ex2(acc[t][1] - m_lo); sum_lo += acc[t][1];
            acc[t][2] = ex2(acc[t][2] - m_hi); sum_hi += acc[t][2];
            acc[t][3] = ex2(acc[t][3] - m_hi); sum_hi += acc[t][3];
        }
        sum_lo += __shfl_xor_sync(0xffffffffu, sum_lo, 1);
        sum_lo += __shfl_xor_sync(0xffffffffu, sum_lo, 2);
        sum_hi += __shfl_xor_sync(0xffffffffu, sum_hi, 1);
        sum_hi += __shfl_xor_sync(0xffffffffu, sum_hi, 2);
        l_lo = l_lo * cr_lo + sum_lo;
        l_hi = l_hi * cr_hi + sum_hi;

#pragma unroll
        for (int nt = 0; nt < 8; nt++) {
            o[nt][0] *= cr_lo; o[nt][1] *= cr_lo;
            o[nt][2] *= cr_hi; o[nt][3] *= cr_hi;
        }

        const unsigned vb = kb + KVT_E * 2;
#pragma unroll
        for (int t2 = 0; t2 < 4; t2++) {
            unsigned aP[4];
            aP[0] = packh2(acc[2 * t2][0],     acc[2 * t2][1]);
            aP[1] = packh2(acc[2 * t2][2],     acc[2 * t2][3]);
            aP[2] = packh2(acc[2 * t2 + 1][0], acc[2 * t2 + 1][1]);
            aP[3] = packh2(acc[2 * t2 + 1][2], acc[2 * t2 + 1][3]);
#pragma unroll
            for (int dp = 0; dp < 4; dp++) {
                unsigned rh[4];
                ldsm_x4t(rh, vb + ((t2 * 16 + (lane & 15)) * TSTR + dp * 16 + koff) * 2);
                unsigned b0[2] = {rh[0], rh[1]}, b1[2] = {rh[2], rh[3]};
                mma_f16(o[2 * dp],     aP, b0);
                mma_f16(o[2 * dp + 1], aP, b1);
            }
        }

        __syncthreads();
        if (kt + 2 < S_LEN / 64) {
            const int c0 = (kt + 2) * 64;
            const unsigned nb = sbase + (BUF0_E + buf * BUFBLK_E) * 2;
#pragma unroll
            for (int j = 0; j < 2; j++) {
                const int idx = tid + j * 256;
                const int row = idx >> 3, ch = idx & 7;
                const unsigned off = (row * TSTR + ch * 8) * 2;
                cpa16(nb + off,             g_Kf + ((size_t)(bh * S_LEN + c0 + row) * DK + ch * 8));
                cpa16(nb + KVT_E * 2 + off, g_Vf + ((size_t)(bh * S_LEN + c0 + row) * DK + ch * 8));
            }
            if (tid < 32) {
                const int arr = tid >> 4, q = tid & 15;
                const float* s = arr ? sn : cs;
                cpa16(sbase + KC_BYTE_OFF + buf * 512 + arr * 256 + q * 16,
                      s + (size_t)bh * S_LEN + c0 + q * 4);
            }
        }
        cp_commit();
    }

    const int b = bh >> 4, h = bh & 15;
    const float inv_lo = 1.f / l_lo;
    const float inv_hi = 1.f / l_hi;
    const int row_lo = q0 + warp * 16 + (lane >> 2);
#pragma unroll
    for (int nt = 0; nt < 8; nt++) {
        const int col = h * DK + nt * 8 + ((lane & 3) << 1);
        *(float2*)&O[((size_t)b * S_LEN + row_lo) * DMODEL + col] =
            make_float2(o[nt][0] * inv_lo, o[nt][1] * inv_lo);
        *(float2*)&O[((size_t)b * S_LEN + row_lo + 8) * DMODEL + col] =
            make_float2(o[nt][2] * inv_hi, o[nt][3] * inv_hi);
    }
}

// ============================================================================
extern "C" void kernel_launch(void* const* d_in, const int* in_sizes, int n_in,
                              void* d_out, int out_size)
{
    const float* x     = (const float*)d_in[0];
    const float* Wq    = (const float*)d_in[1];
    const float* bq    = (const float*)d_in[2];
    const float* Wk    = (const float*)d_in[3];
    const float* bk    = (const float*)d_in[4];
    const float* Wv    = (const float*)d_in[5];
    const float* bv    = (const float*)d_in[6];
    const float* Wo    = (const float*)d_in[7];
    const float* bo    = (const float*)d_in[8];
    const float* Wp    = (const float*)d_in[9];
    const float* bp    = (const float*)d_in[10];
    const float* alpha = (const float*)d_in[11];
    float* out = (float*)d_out;

    __half *pQ, *pK, *pV;
    float *pO, *pc, *ps;
    cudaGetSymbolAddress((void**)&pQ, g_Qf);
    cudaGetSymbolAddress((void**)&pK, g_Kf);
    cudaGetSymbolAddress((void**)&pV, g_Vf);
    cudaGetSymbolAddress((void**)&pO, g_O);
    cudaGetSymbolAddress((void**)&pc, g_cs);
    cudaGetSymbolAddress((void**)&ps, g_sn);

    cudaFuncSetAttribute(gemm_h1<0>, cudaFuncAttributeMaxDynamicSharedMemorySize, MMA_SMEM_BYTES);
    cudaFuncSetAttribute(gemm_h1<1>, cudaFuncAttributeMaxDynamicSharedMemorySize, MMA_SMEM_BYTES);
    cudaFuncSetAttribute(phase_kernel3, cudaFuncAttributeMaxDynamicSharedMemorySize, PHASE_SMEM_BYTES);
    cudaFuncSetAttribute(attn_f16, cudaFuncAttributeMaxDynamicSharedMemorySize, ATT_SMEM_BYTES);

    dim3 g(DMODEL / 128, NTOK / 128);   // (8, 32)

    gemm_h1<1><<<g, 256, MMA_SMEM_BYTES>>>(x, Wq, bq, nullptr, pQ,
                                           0.125f * LOG2E, NTOK, DMODEL, DMODEL);
    gemm_h1<1><<<g, 256, MMA_SMEM_BYTES>>>(x, Wk, bk, nullptr, pK, 1.0f,
                                           NTOK, DMODEL, DMODEL);
    gemm_h1<1><<<g, 256, MMA_SMEM_BYTES>>>(x, Wv, bv, nullptr, pV, 1.0f,
                                           NTOK, DMODEL, DMODEL);
    phase_kernel3<<<NTOK / 16, 256, PHASE_SMEM_BYTES>>>(x, Wp, bp, pc, ps);

    attn_f16<<<dim3(S_LEN / 128, BHALL), 256, ATT_SMEM_BYTES>>>(pc, ps, alpha, pO);

    gemm_h1<0><<<g, 256, MMA_SMEM_BYTES>>>(pO, Wo, bo, out, nullptr, 1.0f,
                                           NTOK, DMODEL, DMODEL);
}

// round 17
// speedup vs baseline: 2.0526x; 1.0629x over previous
#include <cuda_runtime.h>
#include <cuda_bf16.h>
#include <cuda_fp16.h>
#include <math.h>
#include <stdint.h>

#define S_LEN   2048
#define DMODEL  1024
#define NHEADS  16
#define DK      64
#define BATCH   2
#define NTOK    (BATCH * S_LEN)
#define BHALL   (BATCH * NHEADS)
#define LOG2E   1.44269504f

__device__ __align__(256) __half g_Qf[BHALL * S_LEN * DK];
__device__ __align__(256) __half g_Kf[BHALL * S_LEN * DK];
__device__ __align__(256) __half g_Vf[BHALL * S_LEN * DK];
__device__ float g_O[NTOK * DMODEL];
__device__ float g_cs[BHALL * S_LEN];
__device__ float g_sn[BHALL * S_LEN];

// ============================ helpers ============================
__device__ __forceinline__ unsigned sptr(const void* p) {
    return (unsigned)__cvta_generic_to_shared(p);
}
__device__ __forceinline__ void ldsm_x4(unsigned r[4], unsigned sa) {
    asm volatile("ldmatrix.sync.aligned.m8n8.x4.shared.b16 {%0,%1,%2,%3}, [%4];"
                 : "=r"(r[0]), "=r"(r[1]), "=r"(r[2]), "=r"(r[3]) : "r"(sa));
}
__device__ __forceinline__ void ldsm_x4t(unsigned r[4], unsigned sa) {
    asm volatile("ldmatrix.sync.aligned.m8n8.x4.trans.shared.b16 {%0,%1,%2,%3}, [%4];"
                 : "=r"(r[0]), "=r"(r[1]), "=r"(r[2]), "=r"(r[3]) : "r"(sa));
}
__device__ __forceinline__ void mma_f16(float c[4], const unsigned a[4], const unsigned b[2]) {
    asm volatile(
        "mma.sync.aligned.m16n8k16.row.col.f32.f16.f16.f32 "
        "{%0,%1,%2,%3}, {%4,%5,%6,%7}, {%8,%9}, {%0,%1,%2,%3};"
        : "+f"(c[0]), "+f"(c[1]), "+f"(c[2]), "+f"(c[3])
        : "r"(a[0]), "r"(a[1]), "r"(a[2]), "r"(a[3]), "r"(b[0]), "r"(b[1]));
}
__device__ __forceinline__ void cpa16(unsigned d, const void* s) {
    asm volatile("cp.async.cg.shared.global [%0], [%1], 16;" :: "r"(d), "l"(s));
}
__device__ __forceinline__ void cp_commit() { asm volatile("cp.async.commit_group;"); }
template <int N> __device__ __forceinline__ void cp_wait() {
    asm volatile("cp.async.wait_group %0;" :: "n"(N));
}
__device__ __forceinline__ unsigned packh2(float e0, float e1) {
    const __half2 h = __floats2half2_rn(e0, e1);
    return *reinterpret_cast<const unsigned*>(&h);
}
__device__ __forceinline__ float ex2(float x) {
    float r;
    asm("ex2.approx.f32 %0, %1;" : "=f"(r) : "f"(x));
    return r;
}

// ============================================================================
// GEMM single fp16 (R16-proven body).
// MODE 1: fused QKV — z=blockIdx.z selects {Wq,Wk,Wv}/{bq,bk,bv}/{Qf,Kf,Vf};
//         writes __half head-major, val*scl (scl folds 0.125*log2e into Q).
// MODE 0: out projection — fp32 token-major C.
// ============================================================================
#define ASTR 40
#define BSTR 136
#define A_ELEMS (128 * ASTR)
#define B_ELEMS (32 * BSTR)
#define BUF_ELEMS (A_ELEMS + B_ELEMS)
#define MMA_SMEM_BYTES (2 * BUF_ELEMS * 2)

template <int MODE>
__global__ void __launch_bounds__(256) gemm_h1(
    const float* __restrict__ A,
    const float* __restrict__ B0, const float* __restrict__ B1,
    const float* __restrict__ B2,
    const float* __restrict__ bias0, const float* __restrict__ bias1,
    const float* __restrict__ bias2, float* __restrict__ C)
{
    extern __shared__ __half smh[];
    const int tid  = threadIdx.x;
    const int lane = tid & 31;
    const int warp = tid >> 5;
    const int wm = (warp >> 1) * 32;
    const int wn = (warp & 1) * 64;
    const int m0 = blockIdx.y * 128;
    const int n0 = blockIdx.x * 128;
    const int z  = (MODE == 1) ? blockIdx.z : 0;

    const float* B    = (z == 0) ? B0 : (z == 1) ? B1 : B2;
    const float* bias = (z == 0) ? bias0 : (z == 1) ? bias1 : bias2;
    const float scl   = (MODE == 1 && z == 0) ? 0.125f * LOG2E : 1.0f;
    __half* Cf = (MODE == 1) ? ((z == 0) ? g_Qf : (z == 1) ? g_Kf : g_Vf) : nullptr;

    int arow[4], acol[4], brow[4], bcol[4];
#pragma unroll
    for (int j = 0; j < 4; j++) {
        const int idx = tid + j * 256;
        arow[j] = idx >> 3;  acol[j] = (idx & 7) << 2;
        brow[j] = idx >> 5;  bcol[j] = (idx & 31) << 2;
    }

    float4 pa[4], pb[4];
#pragma unroll
    for (int j = 0; j < 4; j++) {
        pa[j] = *(const float4*)&A[(size_t)(m0 + arow[j]) * DMODEL + acol[j]];
        pb[j] = *(const float4*)&B[(size_t)brow[j] * DMODEL + n0 + bcol[j]];
    }
    {
        __half* Ah = smh;
        __half* Bh = smh + A_ELEMS;
#pragma unroll
        for (int j = 0; j < 4; j++) {
            *reinterpret_cast<uint2*>(&Ah[arow[j] * ASTR + acol[j]]) =
                make_uint2(packh2(pa[j].x, pa[j].y), packh2(pa[j].z, pa[j].w));
            *reinterpret_cast<uint2*>(&Bh[brow[j] * BSTR + bcol[j]]) =
                make_uint2(packh2(pb[j].x, pb[j].y), packh2(pb[j].z, pb[j].w));
        }
    }
    __syncthreads();

    float acc[2][8][4];
#pragma unroll
    for (int mt = 0; mt < 2; mt++)
#pragma unroll
        for (int nt = 0; nt < 8; nt++)
#pragma unroll
            for (int e = 0; e < 4; e++) acc[mt][nt][e] = 0.f;

    const int KT = DMODEL / 32;
    for (int kt = 0; kt < KT; ++kt) {
        const int buf = kt & 1;
        if (kt + 1 < KT) {
            const int k0 = (kt + 1) * 32;
#pragma unroll
            for (int j = 0; j < 4; j++) {
                pa[j] = *(const float4*)&A[(size_t)(m0 + arow[j]) * DMODEL + k0 + acol[j]];
                pb[j] = *(const float4*)&B[(size_t)(k0 + brow[j]) * DMODEL + n0 + bcol[j]];
            }
        }

        const __half* Ah = smh + buf * BUF_ELEMS;
        const __half* Bh = smh + buf * BUF_ELEMS + A_ELEMS;

#pragma unroll
        for (int kk = 0; kk < 32; kk += 16) {
            unsigned af[2][4];
#pragma unroll
            for (int mt = 0; mt < 2; mt++) {
                unsigned sa = sptr(&Ah[(wm + mt * 16 + (lane & 15)) * ASTR
                                       + kk + ((lane >> 4) << 3)]);
                ldsm_x4(af[mt], sa);
            }
            unsigned bf[8][2];
#pragma unroll
            for (int np = 0; np < 4; np++) {
                unsigned sb = sptr(&Bh[(kk + (lane & 15)) * BSTR
                                       + wn + np * 16 + ((lane >> 4) << 3)]);
                unsigned r[4];
                ldsm_x4t(r, sb);
                bf[2 * np][0] = r[0]; bf[2 * np][1] = r[1];
                bf[2 * np + 1][0] = r[2]; bf[2 * np + 1][1] = r[3];
            }
#pragma unroll
            for (int mt = 0; mt < 2; mt++)
#pragma unroll
                for (int nt = 0; nt < 8; nt++)
                    mma_f16(acc[mt][nt], af[mt], bf[nt]);
        }

        if (kt + 1 < KT) {
            const int nb = 1 - buf;
            __half* nAh = smh + nb * BUF_ELEMS;
            __half* nBh = smh + nb * BUF_ELEMS + A_ELEMS;
#pragma unroll
            for (int j = 0; j < 4; j++) {
                *reinterpret_cast<uint2*>(&nAh[arow[j] * ASTR + acol[j]]) =
                    make_uint2(packh2(pa[j].x, pa[j].y), packh2(pa[j].z, pa[j].w));
                *reinterpret_cast<uint2*>(&nBh[brow[j] * BSTR + bcol[j]]) =
                    make_uint2(packh2(pb[j].x, pb[j].y), packh2(pb[j].z, pb[j].w));
            }
            __syncthreads();
        }
    }

#pragma unroll
    for (int mt = 0; mt < 2; mt++) {
        const int r0 = m0 + wm + mt * 16 + (lane >> 2);
#pragma unroll
        for (int nt = 0; nt < 8; nt++) {
            const int c = n0 + wn + nt * 8 + ((lane & 3) << 1);
            const float b0v = bias[c], b1v = bias[c + 1];
            const float v00 = acc[mt][nt][0] + b0v;
            const float v01 = acc[mt][nt][1] + b1v;
            const float v10 = acc[mt][nt][2] + b0v;
            const float v11 = acc[mt][nt][3] + b1v;
            if (MODE == 0) {
                *(float2*)&C[(size_t)r0 * DMODEL + c]       = make_float2(v00, v01);
                *(float2*)&C[(size_t)(r0 + 8) * DMODEL + c] = make_float2(v10, v11);
            } else {
                const int s = r0 & 2047;
                const int h = c >> 6, d = c & 63;
                const int bh = (r0 >> 11) * NHEADS + h;
                const size_t i0 = ((size_t)bh * S_LEN + s) * DK + d;
                const size_t i1 = ((size_t)bh * S_LEN + s + 8) * DK + d;
                *(unsigned*)&Cf[i0] = packh2(v00 * scl, v01 * scl);
                *(unsigned*)&Cf[i1] = packh2(v10 * scl, v11 * scl);
            }
        }
    }
}

// ============================ phase kernel ============================
#define WPT_STRIDE 1032
#define PHASE_SMEM_BYTES (16 * WPT_STRIDE * 4)

__global__ void __launch_bounds__(256) phase_kernel3(
    const float* __restrict__ x, const float* __restrict__ Wp,
    const float* __restrict__ bp, float* __restrict__ cs, float* __restrict__ sn)
{
    extern __shared__ float WpT[];
    const int tid = threadIdx.x;
    for (int idx = tid; idx < DMODEL * NHEADS; idx += 256) {
        const int k = idx >> 4, h = idx & 15;
        WpT[h * WPT_STRIDE + k] = Wp[idx];
    }
    __syncthreads();

    const int lane = tid & 31;
    const int warp = tid >> 5;
    const int t0 = blockIdx.x * 16 + warp * 2;

    float a0[NHEADS], a1[NHEADS];
#pragma unroll
    for (int h = 0; h < NHEADS; h++) { a0[h] = 0.f; a1[h] = 0.f; }
#pragma unroll 4
    for (int i = 0; i < 32; ++i) {
        const int k = i * 32 + lane;
        const float x0 = x[(size_t)t0 * DMODEL + k];
        const float x1 = x[(size_t)(t0 + 1) * DMODEL + k];
#pragma unroll
        for (int h = 0; h < NHEADS; h++) {
            const float w = WpT[h * WPT_STRIDE + k];
            a0[h] = fmaf(x0, w, a0[h]);
            a1[h] = fmaf(x1, w, a1[h]);
        }
    }
    float p0 = 0.f, p1 = 0.f;
#pragma unroll
    for (int h = 0; h < NHEADS; h++) {
        float v0 = a0[h], v1 = a1[h];
#pragma unroll
        for (int off = 16; off >= 1; off >>= 1) {
            v0 += __shfl_xor_sync(0xffffffffu, v0, off);
            v1 += __shfl_xor_sync(0xffffffffu, v1, off);
        }
        if (lane == h) { p0 = v0; p1 = v1; }
    }
    if (lane < NHEADS) {
        const float bpl = bp[lane];
#pragma unroll
        for (int u = 0; u < 2; u++) {
            const int t = t0 + u;
            const int bh = (t >> 11) * NHEADS + lane;
            float sv, cv;
            sincosf((u ? p1 : p0) + bpl, &sv, &cv);
            cs[bh * S_LEN + (t & 2047)] = cv;
            sn[bh * S_LEN + (t & 2047)] = sv;
        }
    }
}

// ============================================================================
// Attention (R14-16 proven): single fp16 mma, TQ=128 x TK=64, 2 CTAs/SM.
// ============================================================================
#define TSTR   72
#define QF_E   (128 * TSTR)
#define KVT_E  (64 * TSTR)
#define BUF0_E QF_E
#define BUFBLK_E (2 * KVT_E)
#define KC_BYTE_OFF ((QF_E + 2 * BUFBLK_E) * 2)
#define ATT_SMEM_BYTES (KC_BYTE_OFF + 2 * 128 * 4)

__global__ void __launch_bounds__(256, 2) attn_f16(
    const float* __restrict__ cs, const float* __restrict__ sn,
    const float* __restrict__ alpha, float* __restrict__ O)
{
    extern __shared__ __half smh[];
    const unsigned sbase = sptr(smh);
    const int tid  = threadIdx.x;
    const int lane = tid & 31;
    const int warp = tid >> 5;
    const int bh = blockIdx.y;
    const int q0 = blockIdx.x * 128;

#pragma unroll
    for (int j = 0; j < 4; j++) {
        const int idx = tid + j * 256;
        const int row = idx >> 3, ch = idx & 7;
        cpa16(sbase + (row * TSTR + ch * 8) * 2,
              g_Qf + ((size_t)(bh * S_LEN + q0 + row) * DK + ch * 8));
    }
#pragma unroll 1
    for (int pre = 0; pre < 2; pre++) {
        const int c0 = pre * 64;
        const unsigned kb = sbase + (BUF0_E + pre * BUFBLK_E) * 2;
#pragma unroll
        for (int j = 0; j < 2; j++) {
            const int idx = tid + j * 256;
            const int row = idx >> 3, ch = idx & 7;
            const unsigned off = (row * TSTR + ch * 8) * 2;
            cpa16(kb + off,             g_Kf + ((size_t)(bh * S_LEN + c0 + row) * DK + ch * 8));
            cpa16(kb + KVT_E * 2 + off, g_Vf + ((size_t)(bh * S_LEN + c0 + row) * DK + ch * 8));
        }
        if (tid < 32) {
            const int arr = tid >> 4, q = tid & 15;
            const float* s = arr ? sn : cs;
            cpa16(sbase + KC_BYTE_OFF + pre * 512 + arr * 256 + q * 16,
                  s + (size_t)bh * S_LEN + c0 + q * 4);
        }
        cp_commit();
    }

    const float alp = alpha[bh & (NHEADS - 1)] * LOG2E;
    const int rq_lo = q0 + warp * 16 + (lane >> 2);
    const float aqc_lo = alp * cs[bh * S_LEN + rq_lo];
    const float aqs_lo = alp * sn[bh * S_LEN + rq_lo];
    const float aqc_hi = alp * cs[bh * S_LEN + rq_lo + 8];
    const float aqs_hi = alp * sn[bh * S_LEN + rq_lo + 8];

    cp_wait<1>();
    __syncthreads();

    const int koff = (lane >> 4) << 3;
    const unsigned qrow = (warp * 16 + (lane & 15)) * TSTR;
    unsigned afq[4][4];
#pragma unroll
    for (int ks = 0; ks < 4; ks++)
        ldsm_x4(afq[ks], sbase + (qrow + ks * 16 + koff) * 2);

    float m_lo = -1e30f, m_hi = -1e30f, l_lo = 0.f, l_hi = 0.f;
    float o[8][4];
#pragma unroll
    for (int nt = 0; nt < 8; nt++)
#pragma unroll
        for (int e = 0; e < 4; e++) o[nt][e] = 0.f;

    const float* fkc = (const float*)((const char*)smh + KC_BYTE_OFF);

    for (int kt = 0; kt < S_LEN / 64; ++kt) {
        if (kt) { cp_wait<1>(); __syncthreads(); }
        const int buf = kt & 1;
        const unsigned kb = sbase + (BUF0_E + buf * BUFBLK_E) * 2;

        float acc[8][4];
#pragma unroll
        for (int t = 0; t < 8; t++)
#pragma unroll
            for (int e = 0; e < 4; e++) acc[t][e] = 0.f;

#pragma unroll
        for (int ks = 0; ks < 4; ks++) {
#pragma unroll
            for (int p = 0; p < 4; p++) {
                unsigned rh[4];
                ldsm_x4(rh, kb + ((p * 16 + (lane & 15)) * TSTR + ks * 16 + koff) * 2);
                unsigned b0[2] = {rh[0], rh[2]}, b1[2] = {rh[1], rh[3]};
                mma_f16(acc[2 * p],     afq[ks], b0);
                mma_f16(acc[2 * p + 1], afq[ks], b1);
            }
        }

        const float* kcb = fkc + buf * 128;
        float mx_lo = -1e30f, mx_hi = -1e30f;
#pragma unroll
        for (int t = 0; t < 8; t++) {
            const float2 kc2 = *(const float2*)&kcb[t * 8 + ((lane & 3) << 1)];
            const float2 ks2 = *(const float2*)&kcb[64 + t * 8 + ((lane & 3) << 1)];
            acc[t][0] += aqc_lo * kc2.x + aqs_lo * ks2.x;
            acc[t][1] += aqc_lo * kc2.y + aqs_lo * ks2.y;
            acc[t][2] += aqc_hi * kc2.x + aqs_hi * ks2.x;
            acc[t][3] += aqc_hi * kc2.y + aqs_hi * ks2.y;
            mx_lo = fmaxf(mx_lo, fmaxf(acc[t][0], acc[t][1]));
            mx_hi = fmaxf(mx_hi, fmaxf(acc[t][2], acc[t][3]));
        }
        mx_lo = fmaxf(mx_lo, __shfl_xor_sync(0xffffffffu, mx_lo, 1));
        mx_lo = fmaxf(mx_lo, __shfl_xor_sync(0xffffffffu, mx_lo, 2));
        mx_hi = fmaxf(mx_hi, __shfl_xor_sync(0xffffffffu, mx_hi, 1));
        mx_hi = fmaxf(mx_hi, __shfl_xor_sync(0xffffffffu, mx_hi, 2));

        const float mn_lo = fmaxf(m_lo, mx_lo);
        const float mn_hi = fmaxf(m_hi, mx_hi);
        const float cr_lo = ex2(m_lo - mn_lo);
        const float cr_hi = ex2(m_hi - mn_hi);
        m_lo = mn_lo; m_hi = mn_hi;

        float sum_lo = 0.f, sum_hi = 0.f;
#pragma unroll
        for (int t = 0; t < 8; t++) {
            acc[t][0] = ex2(acc[t][0] - m_lo); sum_lo += acc[t][0];
            acc[t][1] = ex2(acc[t][1] - m_lo); sum_lo += acc[t][1];
            acc[t][2] = ex2(acc[t][2] - m_hi); sum_hi += acc[t][2];
            acc[t][3] = ex2(acc[t][3] - m_hi); sum_hi += acc[t][3];
        }
        sum_lo += __shfl_xor_sync(0xffffffffu, sum_lo, 1);
        sum_lo += __shfl_xor_sync(0xffffffffu, sum_lo, 2);
        sum_hi += __shfl_xor_sync(0xffffffffu, sum_hi, 1);
        sum_hi += __shfl_xor_sync(0xffffffffu, sum_hi, 2);
        l_lo = l_lo * cr_lo + sum_lo;
        l_hi = l_hi * cr_hi + sum_hi;

#pragma unroll
        for (int nt = 0; nt < 8; nt++) {
            o[nt][0] *= cr_lo; o[nt][1] *= cr_lo;
            o[nt][2] *= cr_hi; o[nt][3] *= cr_hi;
        }

        const unsigned vb = kb + KVT_E * 2;
#pragma unroll
        for (int t2 = 0; t2 < 4; t2++) {
            unsigned aP[4];
            aP[0] = packh2(acc[2 * t2][0],     acc[2 * t2][1]);
            aP[1] = packh2(acc[2 * t2][2],     acc[2 * t2][3]);
            aP[2] = packh2(acc[2 * t2 + 1][0], acc[2 * t2 + 1][1]);
            aP[3] = packh2(acc[2 * t2 + 1][2], acc[2 * t2 + 1][3]);
#pragma unroll
            for (int dp = 0; dp < 4; dp++) {
                unsigned rh[4];
                ldsm_x4t(rh, vb + ((t2 * 16 + (lane & 15)) * TSTR + dp * 16 + koff) * 2);
                unsigned b0[2] = {rh[0], rh[1]}, b1[2] = {rh[2], rh[3]};
                mma_f16(o[2 * dp],     aP, b0);
                mma_f16(o[2 * dp + 1], aP, b1);
            }
        }

        __syncthreads();
        if (kt + 2 < S_LEN / 64) {
            const int c0 = (kt + 2) * 64;
            const unsigned nb = sbase + (BUF0_E + buf * BUFBLK_E) * 2;
#pragma unroll
            for (int j = 0; j < 2; j++) {
                const int idx = tid + j * 256;
                const int row = idx >> 3, ch = idx & 7;
                const unsigned off = (row * TSTR + ch * 8) * 2;
                cpa16(nb + off,             g_Kf + ((size_t)(bh * S_LEN + c0 + row) * DK + ch * 8));
                cpa16(nb + KVT_E * 2 + off, g_Vf + ((size_t)(bh * S_LEN + c0 + row) * DK + ch * 8));
            }
            if (tid < 32) {
                const int arr = tid >> 4, q = tid & 15;
                const float* s = arr ? sn : cs;
                cpa16(sbase + KC_BYTE_OFF + buf * 512 + arr * 256 + q * 16,
                      s + (size_t)bh * S_LEN + c0 + q * 4);
            }
        }
        cp_commit();
    }

    const int b = bh >> 4, h = bh & 15;
    const float inv_lo = 1.f / l_lo;
    const float inv_hi = 1.f / l_hi;
    const int row_lo = q0 + warp * 16 + (lane >> 2);
#pragma unroll
    for (int nt = 0; nt < 8; nt++) {
        const int col = h * DK + nt * 8 + ((lane & 3) << 1);
        *(float2*)&O[((size_t)b * S_LEN + row_lo) * DMODEL + col] =
            make_float2(o[nt][0] * inv_lo, o[nt][1] * inv_lo);
        *(float2*)&O[((size_t)b * S_LEN + row_lo + 8) * DMODEL + col] =
            make_float2(o[nt][2] * inv_hi, o[nt][3] * inv_hi);
    }
}

// ============================================================================
extern "C" void kernel_launch(void* const* d_in, const int* in_sizes, int n_in,
                              void* d_out, int out_size)
{
    const float* x     = (const float*)d_in[0];
    const float* Wq    = (const float*)d_in[1];
    const float* bq    = (const float*)d_in[2];
    const float* Wk    = (const float*)d_in[3];
    const float* bk    = (const float*)d_in[4];
    const float* Wv    = (const float*)d_in[5];
    const float* bv    = (const float*)d_in[6];
    const float* Wo    = (const float*)d_in[7];
    const float* bo    = (const float*)d_in[8];
    const float* Wp    = (const float*)d_in[9];
    const float* bp    = (const float*)d_in[10];
    const float* alpha = (const float*)d_in[11];
    float* out = (float*)d_out;

    float *pO, *pc, *ps;
    cudaGetSymbolAddress((void**)&pO, g_O);
    cudaGetSymbolAddress((void**)&pc, g_cs);
    cudaGetSymbolAddress((void**)&ps, g_sn);

    cudaFuncSetAttribute(gemm_h1<0>, cudaFuncAttributeMaxDynamicSharedMemorySize, MMA_SMEM_BYTES);
    cudaFuncSetAttribute(gemm_h1<1>, cudaFuncAttributeMaxDynamicSharedMemorySize, MMA_SMEM_BYTES);
    cudaFuncSetAttribute(phase_kernel3, cudaFuncAttributeMaxDynamicSharedMemorySize, PHASE_SMEM_BYTES);
    cudaFuncSetAttribute(attn_f16, cudaFuncAttributeMaxDynamicSharedMemorySize, ATT_SMEM_BYTES);

    // fused QKV: one launch, z selects W/bias/dst (2.6 waves vs 3 x 0.58)
    gemm_h1<1><<<dim3(8, 32, 3), 256, MMA_SMEM_BYTES>>>(
        x, Wq, Wk, Wv, bq, bk, bv, nullptr);

    phase_kernel3<<<NTOK / 16, 256, PHASE_SMEM_BYTES>>>(x, Wp, bp, pc, ps);

    attn_f16<<<dim3(S_LEN / 128, BHALL), 256, ATT_SMEM_BYTES>>>(pc, ps, alpha, pO);

    gemm_h1<0><<<dim3(8, 32, 1), 256, MMA_SMEM_BYTES>>>(
        pO, Wo, nullptr, nullptr, bo, nullptr, nullptr, out);
}